// round 2
// baseline (speedup 1.0000x reference)
#include <cuda_runtime.h>
#include <math.h>

#define Nn   10000
#define INC  128
#define HIDC 128
#define OUTC 64
#define NH   3
#define NKC  10
#define HC1  (NH*HIDC)   /* 384 */
#define HC2  (NH*OUTC)   /* 192 */
#define EBASE 320000
#define ETOTC (EBASE+Nn) /* 330000 */

// ---------------- scratch (device globals; no allocation allowed) ----------------
__device__ float    g_h1[Nn*HC1];     // layer1 pre-agg features x@W1
__device__ float    g_hl1[Nn*HC1];    // layer1 output after elu
__device__ float    g_agg1[Nn*HC1];
__device__ float    g_h2[Nn*HC2];     // layer2 pre-agg, later layer2 output
__device__ float    g_agg2[Nn*HC2];
__device__ float    g_z[Nn*HC2];
__device__ float    g_as1[Nn*NH], g_ad1[Nn*NH], g_as2[Nn*NH], g_ad2[Nn*NH];
__device__ unsigned g_m1[Nn*NH],  g_m2[Nn*NH];
__device__ float    g_den1[Nn*NH], g_den2[Nn*NH];
__device__ float    g_ex1[ETOTC*NH], g_ex2[ETOTC*NH];
__device__ float    g_ae[2*NH];
__device__ int      g_ei[2*EBASE];    // converted int32 edge index
__device__ int      g_is64;

// order-preserving float<->uint for atomicMax over signed floats
__device__ __forceinline__ unsigned f2o(float f){
    unsigned u = __float_as_uint(f);
    return (u & 0x80000000u) ? ~u : (u | 0x80000000u);
}
__device__ __forceinline__ float o2f(unsigned u){
    return (u & 0x80000000u) ? __uint_as_float(u & 0x7fffffffu) : __uint_as_float(~u);
}

// ---------------- edge-index dtype detect + convert ----------------
// If the buffer is little-endian int64 with node ids < N, every odd 32-bit
// word is zero; for genuine int32 index data the odd words are other node ids
// (virtually never all zero across 64 samples).
__global__ void k_detect(const unsigned* __restrict__ raw){
    if (threadIdx.x == 0){
        int ok64 = 1;
        for (int i = 0; i < 64; i++)
            if (raw[2*i+1] != 0u){ ok64 = 0; break; }
        g_is64 = ok64;
    }
}
__global__ void k_convert(const void* __restrict__ raw, int n){
    int i = blockIdx.x*blockDim.x + threadIdx.x;
    if (i >= n) return;
    if (g_is64) g_ei[i] = (int)((const long long*)raw)[i];
    else        g_ei[i] = ((const int*)raw)[i];
}

// ---------------- misc small kernels ----------------
__global__ void k_zero(float* p, int n){
    int i = blockIdx.x*blockDim.x + threadIdx.x;
    if (i < n) p[i] = 0.f;
}

// a_e constants: ae[h] = sum_c We[0,h*C+c] * att_e[h,c]
__global__ void k_ae(const float* We1, const float* ate1, const float* We2, const float* ate2){
    int t = threadIdx.x;
    if (t < NH){
        float s = 0.f;
        for (int c = 0; c < HIDC; c++) s += We1[t*HIDC+c]*ate1[t*HIDC+c];
        g_ae[t] = s;
    } else if (t < 2*NH){
        int h = t - NH; float s = 0.f;
        for (int c = 0; c < OUTC; c++) s += We2[h*OUTC+c]*ate2[h*OUTC+c];
        g_ae[NH+h] = s;
    }
}

// ---------------- generic 64x64x16 fp32 GEMM (row-major NN) ----------------
template<bool SAN>
__global__ void __launch_bounds__(256) gemm64(const float* __restrict__ A,
                                              const float* __restrict__ B,
                                              float* __restrict__ C,
                                              int M, int Ncol, int K){
    __shared__ float As[16][64];
    __shared__ float Bs[16][64];
    int rb = blockIdx.y*64, cb = blockIdx.x*64;
    int tid = threadIdx.x;
    int tx = tid & 15, ty = tid >> 4;
    float acc[4][4] = {};
    for (int k0 = 0; k0 < K; k0 += 16){
        {
            int r = tid >> 2, k4 = (tid & 3)*4;
            float4 v = make_float4(0.f,0.f,0.f,0.f);
            if (rb + r < M) v = *(const float4*)(A + (size_t)(rb+r)*K + k0 + k4);
            if (SAN){
                v.x = isnan(v.x)?0.f:v.x; v.y = isnan(v.y)?0.f:v.y;
                v.z = isnan(v.z)?0.f:v.z; v.w = isnan(v.w)?0.f:v.w;
            }
            As[k4+0][r]=v.x; As[k4+1][r]=v.y; As[k4+2][r]=v.z; As[k4+3][r]=v.w;
        }
        {
            int kr = tid >> 4, c4 = (tid & 15)*4;
            *(float4*)&Bs[kr][c4] = *(const float4*)(B + (size_t)(k0+kr)*Ncol + cb + c4);
        }
        __syncthreads();
        #pragma unroll
        for (int k = 0; k < 16; k++){
            float4 a4 = *(float4*)&As[k][ty*4];
            float4 b4 = *(float4*)&Bs[k][tx*4];
            float av[4] = {a4.x,a4.y,a4.z,a4.w};
            float bv[4] = {b4.x,b4.y,b4.z,b4.w};
            #pragma unroll
            for (int i = 0; i < 4; i++)
                #pragma unroll
                for (int j = 0; j < 4; j++)
                    acc[i][j] += av[i]*bv[j];
        }
        __syncthreads();
    }
    #pragma unroll
    for (int i = 0; i < 4; i++){
        int row = rb + ty*4 + i;
        if (row < M)
            *(float4*)(C + (size_t)row*Ncol + cb + tx*4) =
                make_float4(acc[i][0],acc[i][1],acc[i][2],acc[i][3]);
    }
}

// ---------------- per-(node,head) attention logits a_s, a_d ----------------
__global__ void k_attn(const float* __restrict__ hfeat, const float* __restrict__ atts,
                       const float* __restrict__ attd, float* __restrict__ as_,
                       float* __restrict__ ad_, int C){
    int gw   = (blockIdx.x*blockDim.x + threadIdx.x) >> 5;
    int lane = threadIdx.x & 31;
    if (gw >= Nn*NH) return;
    int n = gw / NH, hh = gw % NH;
    const float* hp = hfeat + (size_t)n*NH*C + hh*C;
    float s = 0.f, d = 0.f;
    for (int c = lane; c < C; c += 32){
        float v = hp[c];
        s += v*atts[hh*C+c];
        d += v*attd[hh*C+c];
    }
    #pragma unroll
    for (int o = 16; o; o >>= 1){
        s += __shfl_xor_sync(0xffffffffu, s, o);
        d += __shfl_xor_sync(0xffffffffu, d, o);
    }
    if (lane == 0){ as_[gw] = s; ad_[gw] = d; }
}

// ---------------- edge kernels: segment softmax ----------------
__global__ void k_edge_max(const float* __restrict__ ea,
                           const float* __restrict__ as_, const float* __restrict__ ad_,
                           unsigned* __restrict__ m, int E, int aeoff){
    int e = blockIdx.x*blockDim.x + threadIdx.x;
    if (e >= E + Nn) return;
    int s, d; float w;
    if (e < E){ s = g_ei[e]; d = g_ei[E+e]; w = ea[e]; }
    else      { s = e - E; d = s; w = 1.f; }
    #pragma unroll
    for (int h = 0; h < NH; h++){
        float a = as_[s*NH+h] + ad_[d*NH+h] + w*g_ae[aeoff+h];
        a = a > 0.f ? a : 0.2f*a;            // leaky_relu(0.2)
        atomicMax(&m[d*NH+h], f2o(a));
    }
}

__global__ void k_edge_exp(const float* __restrict__ ea,
                           const float* __restrict__ as_, const float* __restrict__ ad_,
                           const unsigned* __restrict__ m, float* __restrict__ exbuf,
                           float* __restrict__ den, int E, int aeoff){
    int e = blockIdx.x*blockDim.x + threadIdx.x;
    if (e >= E + Nn) return;
    int s, d; float w;
    if (e < E){ s = g_ei[e]; d = g_ei[E+e]; w = ea[e]; }
    else      { s = e - E; d = s; w = 1.f; }
    #pragma unroll
    for (int h = 0; h < NH; h++){
        float a = as_[s*NH+h] + ad_[d*NH+h] + w*g_ae[aeoff+h];
        a = a > 0.f ? a : 0.2f*a;
        float x = __expf(a - o2f(m[d*NH+h]));
        exbuf[(size_t)e*NH+h] = x;
        atomicAdd(&den[d*NH+h], x);
    }
}

// turn exbuf into coefficients: ex / (den[dst]+1e-16)
__global__ void k_coef(const float* __restrict__ den, float* __restrict__ exbuf, int E){
    int i = blockIdx.x*blockDim.x + threadIdx.x;
    if (i >= (E+Nn)*NH) return;
    int e = i / NH, h = i - e*NH;
    int d = (e < E) ? g_ei[E+e] : (e - E);
    exbuf[i] = exbuf[i] / (den[d*NH+h] + 1e-16f);
}

// ---------------- weighted message scatter: agg[dst] += h[src] * coef ----------------
template<int C>
__global__ void k_scatter(const float* __restrict__ hfeat,
                          const float* __restrict__ coef, float* __restrict__ agg, int E){
    int e = blockIdx.x;
    int t = threadIdx.x;            // blockDim = NH*C
    int s, d;
    if (e < E){ s = g_ei[e]; d = g_ei[E+e]; }
    else      { s = e - E; d = s; }
    int h = t / C;
    float cf = coef[(size_t)e*NH + h];
    atomicAdd(&agg[(size_t)d*(NH*C) + t], hfeat[(size_t)s*(NH*C) + t] * cf);
}

// ---------------- bias + optional ELU ----------------
__global__ void k_biasact(const float* __restrict__ agg, const float* __restrict__ b,
                          float* __restrict__ o, int total, int ncol, int do_elu){
    int i = blockIdx.x*blockDim.x + threadIdx.x;
    if (i >= total) return;
    float v = agg[i] + b[i % ncol];
    if (do_elu) v = v > 0.f ? v : expm1f(v);
    o[i] = v;
}

// ---------------- L2 normalize rows; write z to scratch AND to output tail ----------------
__global__ void k_norm(const float* __restrict__ h, float* __restrict__ z,
                       float* __restrict__ zo){
    int gw   = (blockIdx.x*blockDim.x + threadIdx.x) >> 5;
    int lane = threadIdx.x & 31;
    if (gw >= Nn) return;
    const float* r = h + (size_t)gw*HC2;
    float s = 0.f;
    for (int c = lane; c < HC2; c += 32){ float v = r[c]; s += v*v; }
    #pragma unroll
    for (int o = 16; o; o >>= 1) s += __shfl_xor_sync(0xffffffffu, s, o);
    float inv = 1.f / fmaxf(sqrtf(s), 1e-12f);
    for (int c = lane; c < HC2; c += 32){
        float v = r[c]*inv;
        z[(size_t)gw*HC2+c]  = v;
        zo[(size_t)gw*HC2+c] = v;
    }
}

// ---------------- p = softmax(z @ Wp + bp) ----------------
__global__ void k_p(const float* __restrict__ z, const float* __restrict__ Wp,
                    const float* __restrict__ bp, float* __restrict__ P){
    __shared__ float sW[HC2*NKC];
    __shared__ float sb[NKC];
    for (int i = threadIdx.x; i < HC2*NKC; i += blockDim.x) sW[i] = Wp[i];
    if (threadIdx.x < NKC) sb[threadIdx.x] = bp[threadIdx.x];
    __syncthreads();
    int n = blockIdx.x*blockDim.x + threadIdx.x;
    if (n >= Nn) return;
    float lg[NKC];
    #pragma unroll
    for (int k = 0; k < NKC; k++) lg[k] = sb[k];
    const float* zr = z + (size_t)n*HC2;
    for (int c = 0; c < HC2; c++){
        float v = zr[c];
        #pragma unroll
        for (int k = 0; k < NKC; k++) lg[k] += v*sW[c*NKC+k];
    }
    float mx = lg[0];
    #pragma unroll
    for (int k = 1; k < NKC; k++) mx = fmaxf(mx, lg[k]);
    float sum = 0.f;
    #pragma unroll
    for (int k = 0; k < NKC; k++){ lg[k] = __expf(lg[k]-mx); sum += lg[k]; }
    float inv = 1.f/sum;
    #pragma unroll
    for (int k = 0; k < NKC; k++) P[(size_t)n*NKC+k] = lg[k]*inv;
}

// ---------------- A_hat = z z^T : 128x128x16 fp32 SGEMM (NT) ----------------
__global__ void __launch_bounds__(256) k_syrk(const float* __restrict__ Z,
                                              float* __restrict__ C, int M, int K){
    __shared__ float As[16][128];
    __shared__ float Bs[16][128];
    int rb = blockIdx.y*128, cb = blockIdx.x*128;
    int tid = threadIdx.x;
    int tx = tid & 15, ty = tid >> 4;
    float acc[8][8] = {};
    for (int k0 = 0; k0 < K; k0 += 16){
        int r = tid >> 2, k4 = (tid & 3)*4;
        #pragma unroll
        for (int hlf = 0; hlf < 2; hlf++){
            int rr = r + hlf*64;
            float4 va = make_float4(0.f,0.f,0.f,0.f);
            float4 vb = va;
            if (rb + rr < M) va = *(const float4*)(Z + (size_t)(rb+rr)*K + k0 + k4);
            if (cb + rr < M) vb = *(const float4*)(Z + (size_t)(cb+rr)*K + k0 + k4);
            As[k4+0][rr]=va.x; As[k4+1][rr]=va.y; As[k4+2][rr]=va.z; As[k4+3][rr]=va.w;
            Bs[k4+0][rr]=vb.x; Bs[k4+1][rr]=vb.y; Bs[k4+2][rr]=vb.z; Bs[k4+3][rr]=vb.w;
        }
        __syncthreads();
        #pragma unroll
        for (int k = 0; k < 16; k++){
            float a[8], b[8];
            *(float4*)(a)   = *(float4*)&As[k][ty*8];
            *(float4*)(a+4) = *(float4*)&As[k][ty*8+4];
            *(float4*)(b)   = *(float4*)&Bs[k][tx*8];
            *(float4*)(b+4) = *(float4*)&Bs[k][tx*8+4];
            #pragma unroll
            for (int i = 0; i < 8; i++)
                #pragma unroll
                for (int j = 0; j < 8; j++)
                    acc[i][j] += a[i]*b[j];
        }
        __syncthreads();
    }
    #pragma unroll
    for (int i = 0; i < 8; i++){
        int row = rb + ty*8 + i;
        if (row >= M) continue;
        int c0 = cb + tx*8;
        if (c0 < M)
            *(float4*)(C + (size_t)row*M + c0) =
                make_float4(acc[i][0],acc[i][1],acc[i][2],acc[i][3]);
        if (c0 + 4 < M)
            *(float4*)(C + (size_t)row*M + c0 + 4) =
                make_float4(acc[i][4],acc[i][5],acc[i][6],acc[i][7]);
    }
}

// ---------------- launch ----------------
extern "C" void kernel_launch(void* const* d_in, const int* in_sizes, int n_in,
                              void* d_out, int out_size){
    const float*     x   = (const float*)d_in[0];
    const void*      ei  = d_in[1];
    const float*     ea  = (const float*)d_in[2];
    const float*     W1  = (const float*)d_in[3];
    const float*     as1 = (const float*)d_in[4];
    const float*     ad1 = (const float*)d_in[5];
    const float*     We1 = (const float*)d_in[6];
    const float*     ae1 = (const float*)d_in[7];
    const float*     b1  = (const float*)d_in[8];
    const float*     W2  = (const float*)d_in[9];
    const float*     as2 = (const float*)d_in[10];
    const float*     ad2 = (const float*)d_in[11];
    const float*     We2 = (const float*)d_in[12];
    const float*     ae2 = (const float*)d_in[13];
    const float*     b2  = (const float*)d_in[14];
    const float*     Wp  = (const float*)d_in[15];
    const float*     bp  = (const float*)d_in[16];

    int E  = in_sizes[1]/2;
    if (E > EBASE) E = EBASE;
    int ET = E + Nn;

    float* out  = (float*)d_out;
    float* Ahat = out;
    float* P    = out + (size_t)Nn*Nn;
    float* Zo   = P + (size_t)Nn*NKC;

    float *h1, *hl1, *agg1, *h2p, *agg2, *zb;
    float *pas1, *pad1, *pas2, *pad2, *den1, *den2, *ex1, *ex2;
    unsigned *m1, *m2;
    cudaGetSymbolAddress((void**)&h1,   g_h1);
    cudaGetSymbolAddress((void**)&hl1,  g_hl1);
    cudaGetSymbolAddress((void**)&agg1, g_agg1);
    cudaGetSymbolAddress((void**)&h2p,  g_h2);
    cudaGetSymbolAddress((void**)&agg2, g_agg2);
    cudaGetSymbolAddress((void**)&zb,   g_z);
    cudaGetSymbolAddress((void**)&pas1, g_as1);
    cudaGetSymbolAddress((void**)&pad1, g_ad1);
    cudaGetSymbolAddress((void**)&pas2, g_as2);
    cudaGetSymbolAddress((void**)&pad2, g_ad2);
    cudaGetSymbolAddress((void**)&den1, g_den1);
    cudaGetSymbolAddress((void**)&den2, g_den2);
    cudaGetSymbolAddress((void**)&ex1,  g_ex1);
    cudaGetSymbolAddress((void**)&ex2,  g_ex2);
    cudaGetSymbolAddress((void**)&m1,   g_m1);
    cudaGetSymbolAddress((void**)&m2,   g_m2);

    // edge index dtype-robust conversion to int32
    k_detect<<<1, 32>>>((const unsigned*)ei);
    k_convert<<<(2*E + 255)/256, 256>>>(ei, 2*E);

    k_ae<<<1, 32>>>(We1, ae1, We2, ae2);

    // -------- layer 1 --------
    gemm64<true><<<dim3(HC1/64, (Nn+63)/64), 256>>>(x, W1, h1, Nn, HC1, INC);
    k_attn<<<(Nn*NH*32 + 255)/256, 256>>>(h1, as1, ad1, pas1, pad1, HIDC);

    k_zero<<<(Nn*NH + 255)/256, 256>>>((float*)m1, Nn*NH);
    k_zero<<<(Nn*NH + 255)/256, 256>>>(den1, Nn*NH);
    k_zero<<<(Nn*HC1 + 255)/256, 256>>>(agg1, Nn*HC1);

    k_edge_max<<<(ET + 255)/256, 256>>>(ea, pas1, pad1, m1, E, 0);
    k_edge_exp<<<(ET + 255)/256, 256>>>(ea, pas1, pad1, m1, ex1, den1, E, 0);
    k_coef<<<(ET*NH + 255)/256, 256>>>(den1, ex1, E);
    k_scatter<HIDC><<<ET, NH*HIDC>>>(h1, ex1, agg1, E);
    k_biasact<<<(Nn*HC1 + 255)/256, 256>>>(agg1, b1, hl1, Nn*HC1, HC1, 1);

    // -------- layer 2 --------
    gemm64<false><<<dim3(HC2/64, (Nn+63)/64), 256>>>(hl1, W2, h2p, Nn, HC2, HC1);
    k_attn<<<(Nn*NH*32 + 255)/256, 256>>>(h2p, as2, ad2, pas2, pad2, OUTC);

    k_zero<<<(Nn*NH + 255)/256, 256>>>((float*)m2, Nn*NH);
    k_zero<<<(Nn*NH + 255)/256, 256>>>(den2, Nn*NH);
    k_zero<<<(Nn*HC2 + 255)/256, 256>>>(agg2, Nn*HC2);

    k_edge_max<<<(ET + 255)/256, 256>>>(ea, pas2, pad2, m2, E, NH);
    k_edge_exp<<<(ET + 255)/256, 256>>>(ea, pas2, pad2, m2, ex2, den2, E, NH);
    k_coef<<<(ET*NH + 255)/256, 256>>>(den2, ex2, E);
    k_scatter<OUTC><<<ET, NH*OUTC>>>(h2p, ex2, agg2, E);
    k_biasact<<<(Nn*HC2 + 255)/256, 256>>>(agg2, b2, h2p, Nn*HC2, HC2, 0);

    // -------- head --------
    k_norm<<<(Nn*32 + 255)/256, 256>>>(h2p, zb, Zo);
    k_p<<<(Nn + 255)/256, 256>>>(zb, Wp, bp, P);
    k_syrk<<<dim3((Nn+127)/128, (Nn+127)/128), 256>>>(zb, Ahat, Nn, HC2);
}

// round 7
// speedup vs baseline: 1.4936x; 1.4936x over previous
#include <cuda_runtime.h>
#include <cuda_bf16.h>
#include <stdint.h>
#include <math.h>

#define Nn   10000
#define INC  128
#define HIDC 128
#define OUTC 64
#define NH   3
#define NKC  10
#define HC1  (NH*HIDC)   /* 384 */
#define HC2  (NH*OUTC)   /* 192 */
#define EBASE 320000
#define ETOTC (EBASE+Nn) /* 330000 */

#define MPAD 10112       /* 79*128 */
#define KCAT 576         /* 3*HC2 */
#define BK   64
#define NIT  (KCAT/BK)   /* 9 */
#define SROW 72          /* smem row stride in bf16 (144B): conflict-free frags */
#define TILEB (128*SROW*2)   /* 18432 B per tile */
#define BUFB  (2*TILEB)      /* 36864 B per buffer (A+B) */

// ---------------- scratch (device globals; no allocation allowed) ----------------
__device__ float    g_h1[Nn*HC1];
__device__ float    g_hl1[Nn*HC1];
__device__ float    g_agg1[Nn*HC1];
__device__ float    g_h2[Nn*HC2];
__device__ float    g_agg2[Nn*HC2];
__device__ float    g_z[Nn*HC2];
__device__ float    g_as1[Nn*NH], g_ad1[Nn*NH], g_as2[Nn*NH], g_ad2[Nn*NH];
__device__ unsigned g_m1[Nn*NH],  g_m2[Nn*NH];
__device__ float    g_den1[Nn*NH], g_den2[Nn*NH];
__device__ float    g_ex1[ETOTC*NH], g_ex2[ETOTC*NH];
__device__ float    g_ae[2*NH];
__device__ int      g_ei[2*EBASE];
__device__ int      g_is64;
__device__ unsigned short g_zA[(size_t)MPAD*KCAT];   // bf16 [hi|hi|lo]
__device__ unsigned short g_zB[(size_t)MPAD*KCAT];   // bf16 [hi|lo|hi]

// order-preserving float<->uint for atomicMax over signed floats
__device__ __forceinline__ unsigned f2o(float f){
    unsigned u = __float_as_uint(f);
    return (u & 0x80000000u) ? ~u : (u | 0x80000000u);
}
__device__ __forceinline__ float o2f(unsigned u){
    return (u & 0x80000000u) ? __uint_as_float(u & 0x7fffffffu) : __uint_as_float(~u);
}

// ---------------- edge-index dtype detect + convert ----------------
__global__ void k_detect(const unsigned* __restrict__ raw){
    if (threadIdx.x == 0){
        int ok64 = 1;
        for (int i = 0; i < 64; i++)
            if (raw[2*i+1] != 0u){ ok64 = 0; break; }
        g_is64 = ok64;
    }
}
__global__ void k_convert(const void* __restrict__ raw, int n){
    int i = blockIdx.x*blockDim.x + threadIdx.x;
    if (i >= n) return;
    if (g_is64) g_ei[i] = (int)((const long long*)raw)[i];
    else        g_ei[i] = ((const int*)raw)[i];
}

// ---------------- misc ----------------
__global__ void k_zero(float* p, int n){
    int i = blockIdx.x*blockDim.x + threadIdx.x;
    if (i < n) p[i] = 0.f;
}

__global__ void k_ae(const float* We1, const float* ate1, const float* We2, const float* ate2){
    int t = threadIdx.x;
    if (t < NH){
        float s = 0.f;
        for (int c = 0; c < HIDC; c++) s += We1[t*HIDC+c]*ate1[t*HIDC+c];
        g_ae[t] = s;
    } else if (t < 2*NH){
        int h = t - NH; float s = 0.f;
        for (int c = 0; c < OUTC; c++) s += We2[h*OUTC+c]*ate2[h*OUTC+c];
        g_ae[NH+h] = s;
    }
}

// ---------------- generic 64x64x16 fp32 GEMM (row-major NN) ----------------
template<bool SAN>
__global__ void __launch_bounds__(256) gemm64(const float* __restrict__ A,
                                              const float* __restrict__ B,
                                              float* __restrict__ C,
                                              int M, int Ncol, int K){
    __shared__ float As[16][64];
    __shared__ float Bs[16][64];
    int rb = blockIdx.y*64, cb = blockIdx.x*64;
    int tid = threadIdx.x;
    int tx = tid & 15, ty = tid >> 4;
    float acc[4][4] = {};
    for (int k0 = 0; k0 < K; k0 += 16){
        {
            int r = tid >> 2, k4 = (tid & 3)*4;
            float4 v = make_float4(0.f,0.f,0.f,0.f);
            if (rb + r < M) v = *(const float4*)(A + (size_t)(rb+r)*K + k0 + k4);
            if (SAN){
                v.x = isnan(v.x)?0.f:v.x; v.y = isnan(v.y)?0.f:v.y;
                v.z = isnan(v.z)?0.f:v.z; v.w = isnan(v.w)?0.f:v.w;
            }
            As[k4+0][r]=v.x; As[k4+1][r]=v.y; As[k4+2][r]=v.z; As[k4+3][r]=v.w;
        }
        {
            int kr = tid >> 4, c4 = (tid & 15)*4;
            *(float4*)&Bs[kr][c4] = *(const float4*)(B + (size_t)(k0+kr)*Ncol + cb + c4);
        }
        __syncthreads();
        #pragma unroll
        for (int k = 0; k < 16; k++){
            float4 a4 = *(float4*)&As[k][ty*4];
            float4 b4 = *(float4*)&Bs[k][tx*4];
            float av[4] = {a4.x,a4.y,a4.z,a4.w};
            float bv[4] = {b4.x,b4.y,b4.z,b4.w};
            #pragma unroll
            for (int i = 0; i < 4; i++)
                #pragma unroll
                for (int j = 0; j < 4; j++)
                    acc[i][j] += av[i]*bv[j];
        }
        __syncthreads();
    }
    #pragma unroll
    for (int i = 0; i < 4; i++){
        int row = rb + ty*4 + i;
        if (row < M)
            *(float4*)(C + (size_t)row*Ncol + cb + tx*4) =
                make_float4(acc[i][0],acc[i][1],acc[i][2],acc[i][3]);
    }
}

// ---------------- attention logits ----------------
__global__ void k_attn(const float* __restrict__ hfeat, const float* __restrict__ atts,
                       const float* __restrict__ attd, float* __restrict__ as_,
                       float* __restrict__ ad_, int C){
    int gw   = (blockIdx.x*blockDim.x + threadIdx.x) >> 5;
    int lane = threadIdx.x & 31;
    if (gw >= Nn*NH) return;
    int n = gw / NH, hh = gw % NH;
    const float* hp = hfeat + (size_t)n*NH*C + hh*C;
    float s = 0.f, d = 0.f;
    for (int c = lane; c < C; c += 32){
        float v = hp[c];
        s += v*atts[hh*C+c];
        d += v*attd[hh*C+c];
    }
    #pragma unroll
    for (int o = 16; o; o >>= 1){
        s += __shfl_xor_sync(0xffffffffu, s, o);
        d += __shfl_xor_sync(0xffffffffu, d, o);
    }
    if (lane == 0){ as_[gw] = s; ad_[gw] = d; }
}

// ---------------- edge segment softmax ----------------
__global__ void k_edge_max(const float* __restrict__ ea,
                           const float* __restrict__ as_, const float* __restrict__ ad_,
                           unsigned* __restrict__ m, int E, int aeoff){
    int e = blockIdx.x*blockDim.x + threadIdx.x;
    if (e >= E + Nn) return;
    int s, d; float w;
    if (e < E){ s = g_ei[e]; d = g_ei[E+e]; w = ea[e]; }
    else      { s = e - E; d = s; w = 1.f; }
    #pragma unroll
    for (int h = 0; h < NH; h++){
        float a = as_[s*NH+h] + ad_[d*NH+h] + w*g_ae[aeoff+h];
        a = a > 0.f ? a : 0.2f*a;
        atomicMax(&m[d*NH+h], f2o(a));
    }
}

__global__ void k_edge_exp(const float* __restrict__ ea,
                           const float* __restrict__ as_, const float* __restrict__ ad_,
                           const unsigned* __restrict__ m, float* __restrict__ exbuf,
                           float* __restrict__ den, int E, int aeoff){
    int e = blockIdx.x*blockDim.x + threadIdx.x;
    if (e >= E + Nn) return;
    int s, d; float w;
    if (e < E){ s = g_ei[e]; d = g_ei[E+e]; w = ea[e]; }
    else      { s = e - E; d = s; w = 1.f; }
    #pragma unroll
    for (int h = 0; h < NH; h++){
        float a = as_[s*NH+h] + ad_[d*NH+h] + w*g_ae[aeoff+h];
        a = a > 0.f ? a : 0.2f*a;
        float x = __expf(a - o2f(m[d*NH+h]));
        exbuf[(size_t)e*NH+h] = x;
        atomicAdd(&den[d*NH+h], x);
    }
}

__global__ void k_coef(const float* __restrict__ den, float* __restrict__ exbuf, int E){
    int i = blockIdx.x*blockDim.x + threadIdx.x;
    if (i >= (E+Nn)*NH) return;
    int e = i / NH, h = i - e*NH;
    int d = (e < E) ? g_ei[E+e] : (e - E);
    exbuf[i] = exbuf[i] / (den[d*NH+h] + 1e-16f);
}

// ---------------- weighted message scatter ----------------
template<int C>
__global__ void k_scatter(const float* __restrict__ hfeat,
                          const float* __restrict__ coef, float* __restrict__ agg, int E){
    int e = blockIdx.x;
    int t = threadIdx.x;
    int s, d;
    if (e < E){ s = g_ei[e]; d = g_ei[E+e]; }
    else      { s = e - E; d = s; }
    int h = t / C;
    float cf = coef[(size_t)e*NH + h];
    atomicAdd(&agg[(size_t)d*(NH*C) + t], hfeat[(size_t)s*(NH*C) + t] * cf);
}

// ---------------- bias + optional ELU ----------------
__global__ void k_biasact(const float* __restrict__ agg, const float* __restrict__ b,
                          float* __restrict__ o, int total, int ncol, int do_elu){
    int i = blockIdx.x*blockDim.x + threadIdx.x;
    if (i >= total) return;
    float v = agg[i] + b[i % ncol];
    if (do_elu) v = v > 0.f ? v : expm1f(v);
    o[i] = v;
}

// ---------------- L2 normalize ----------------
__global__ void k_norm(const float* __restrict__ h, float* __restrict__ z,
                       float* __restrict__ zo){
    int gw   = (blockIdx.x*blockDim.x + threadIdx.x) >> 5;
    int lane = threadIdx.x & 31;
    if (gw >= Nn) return;
    const float* r = h + (size_t)gw*HC2;
    float s = 0.f;
    for (int c = lane; c < HC2; c += 32){ float v = r[c]; s += v*v; }
    #pragma unroll
    for (int o = 16; o; o >>= 1) s += __shfl_xor_sync(0xffffffffu, s, o);
    float inv = 1.f / fmaxf(sqrtf(s), 1e-12f);
    for (int c = lane; c < HC2; c += 32){
        float v = r[c]*inv;
        z[(size_t)gw*HC2+c]  = v;
        zo[(size_t)gw*HC2+c] = v;
    }
}

// ---------------- p = softmax(z @ Wp + bp) ----------------
__global__ void k_p(const float* __restrict__ z, const float* __restrict__ Wp,
                    const float* __restrict__ bp, float* __restrict__ P){
    __shared__ float sW[HC2*NKC];
    __shared__ float sb[NKC];
    for (int i = threadIdx.x; i < HC2*NKC; i += blockDim.x) sW[i] = Wp[i];
    if (threadIdx.x < NKC) sb[threadIdx.x] = bp[threadIdx.x];
    __syncthreads();
    int n = blockIdx.x*blockDim.x + threadIdx.x;
    if (n >= Nn) return;
    float lg[NKC];
    #pragma unroll
    for (int k = 0; k < NKC; k++) lg[k] = sb[k];
    const float* zr = z + (size_t)n*HC2;
    for (int c = 0; c < HC2; c++){
        float v = zr[c];
        #pragma unroll
        for (int k = 0; k < NKC; k++) lg[k] += v*sW[c*NKC+k];
    }
    float mx = lg[0];
    #pragma unroll
    for (int k = 1; k < NKC; k++) mx = fmaxf(mx, lg[k]);
    float sum = 0.f;
    #pragma unroll
    for (int k = 0; k < NKC; k++){ lg[k] = __expf(lg[k]-mx); sum += lg[k]; }
    float inv = 1.f/sum;
    #pragma unroll
    for (int k = 0; k < NKC; k++) P[(size_t)n*NKC+k] = lg[k]*inv;
}

// ---------------- pack z into split-bf16 operands ----------------
// zA = [hi | hi | lo], zB = [hi | lo | hi]; rows >= Nn zero-padded.
__global__ void k_pack(const float* __restrict__ z, unsigned short* __restrict__ ZA,
                       unsigned short* __restrict__ ZB){
    int i = blockIdx.x*blockDim.x + threadIdx.x;
    if (i >= MPAD*HC2) return;
    int n = i / HC2, c = i - n*HC2;
    float v = (n < Nn) ? z[(size_t)n*HC2 + c] : 0.f;
    __nv_bfloat16 hib = __float2bfloat16(v);
    float hif = __bfloat162float(hib);
    __nv_bfloat16 lob = __float2bfloat16(v - hif);
    unsigned short hi = __bfloat16_as_ushort(hib);
    unsigned short lo = __bfloat16_as_ushort(lob);
    size_t base = (size_t)n*KCAT + c;
    ZA[base]         = hi;
    ZA[base + HC2]   = hi;
    ZA[base + 2*HC2] = lo;
    ZB[base]         = hi;
    ZB[base + HC2]   = lo;
    ZB[base + 2*HC2] = hi;
}

// ---------------- helpers ----------------
__device__ __forceinline__ uint32_t smem_u32(const void* p){
    uint32_t a;
    asm("{ .reg .u64 t; cvta.to.shared.u64 t, %1; cvt.u32.u64 %0, t; }" : "=r"(a) : "l"(p));
    return a;
}
__device__ __forceinline__ void cpasync16(uint32_t dst, const void* src){
    asm volatile("cp.async.cg.shared.global [%0], [%1], 16;" :: "r"(dst), "l"(src));
}
__device__ __forceinline__ void cp_commit(){
    asm volatile("cp.async.commit_group;");
}
template<int N>
__device__ __forceinline__ void cp_wait(){
    asm volatile("cp.async.wait_group %0;" :: "n"(N));
}
__device__ __forceinline__ void mma16816(float* c, const uint32_t* a, const uint32_t* b){
    asm volatile(
        "mma.sync.aligned.m16n8k16.row.col.f32.bf16.bf16.f32 "
        "{%0,%1,%2,%3}, {%4,%5,%6,%7}, {%8,%9}, {%0,%1,%2,%3};"
        : "+f"(c[0]), "+f"(c[1]), "+f"(c[2]), "+f"(c[3])
        : "r"(a[0]), "r"(a[1]), "r"(a[2]), "r"(a[3]), "r"(b[0]), "r"(b[1]));
}

// async-load one 128xBK tile pair (A rows rb.., B rows cb..) for k-chunk kc
__device__ __forceinline__ void tile_load(const char* __restrict__ GA,
                                          const char* __restrict__ GB,
                                          uint32_t sA, uint32_t sB,
                                          int rb, int cb, int kc, int tid){
    #pragma unroll
    for (int i = 0; i < 4; i++){
        int chunk = tid + i*256;          // 1024 chunks of 16B per tile
        int row = chunk >> 3, seg = chunk & 7;
        size_t gofs = ((size_t)KCAT*row + kc*BK + seg*8) * 2;
        cpasync16(sA + row*(SROW*2) + seg*16, GA + (size_t)(rb)*KCAT*2 + gofs);
        cpasync16(sB + row*(SROW*2) + seg*16, GB + (size_t)(cb)*KCAT*2 + gofs);
    }
}

// ---------------- A_hat = zA zB^T via mma.sync bf16, fp32 accum ----------------
__global__ void __launch_bounds__(256) k_syrk_mma(const char* __restrict__ ZA,
                                                  const char* __restrict__ ZB,
                                                  float* __restrict__ C){
    extern __shared__ char dsm[];
    uint32_t s0 = smem_u32(dsm);

    int tid  = threadIdx.x;
    int wid  = tid >> 5, lane = tid & 31;
    int gid  = lane >> 2, tig = lane & 3;
    int mwarp = (wid & 1) * 64;       // 2 warp-rows
    int nwarp = (wid >> 1) * 32;      // 4 warp-cols
    int rb = blockIdx.y * 128, cb = blockIdx.x * 128;

    float acc[4][4][4];
    #pragma unroll
    for (int a = 0; a < 4; a++)
        #pragma unroll
        for (int b = 0; b < 4; b++)
            #pragma unroll
            for (int c = 0; c < 4; c++) acc[a][b][c] = 0.f;

    tile_load(ZA, ZB, s0, s0 + TILEB, rb, cb, 0, tid);
    cp_commit();

    for (int it = 0; it < NIT; it++){
        int s = it & 1;
        if (it + 1 < NIT){
            int ns = (it + 1) & 1;
            tile_load(ZA, ZB, s0 + ns*BUFB, s0 + ns*BUFB + TILEB, rb, cb, it + 1, tid);
            cp_commit();
            cp_wait<1>();
        } else {
            cp_wait<0>();
        }
        __syncthreads();

        const uint32_t* As32 = (const uint32_t*)(dsm + s*BUFB);
        const uint32_t* Bs32 = (const uint32_t*)(dsm + s*BUFB + TILEB);

        #pragma unroll
        for (int kk = 0; kk < BK/16; kk++){
            uint32_t af[4][4];
            #pragma unroll
            for (int mi = 0; mi < 4; mi++){
                const uint32_t* base = As32 + (size_t)(mwarp + mi*16 + gid)*(SROW/2) + tig + kk*8;
                af[mi][0] = base[0];
                af[mi][1] = base[8*(SROW/2)];
                af[mi][2] = base[4];
                af[mi][3] = base[8*(SROW/2) + 4];
            }
            uint32_t bf[4][2];
            #pragma unroll
            for (int ni = 0; ni < 4; ni++){
                const uint32_t* bb = Bs32 + (size_t)(nwarp + ni*8 + gid)*(SROW/2) + tig + kk*8;
                bf[ni][0] = bb[0];
                bf[ni][1] = bb[4];
            }
            #pragma unroll
            for (int mi = 0; mi < 4; mi++)
                #pragma unroll
                for (int ni = 0; ni < 4; ni++)
                    mma16816(acc[mi][ni], af[mi], bf[ni]);
        }
        __syncthreads();
    }

    // epilogue: documented c-frag layout
    #pragma unroll
    for (int mi = 0; mi < 4; mi++){
        int r0 = rb + mwarp + mi*16 + gid;
        int r1 = r0 + 8;
        #pragma unroll
        for (int ni = 0; ni < 4; ni++){
            int col = cb + nwarp + ni*8 + tig*2;
            if (col + 1 < Nn){
                if (r0 < Nn)
                    *(float2*)(C + (size_t)r0*Nn + col) = make_float2(acc[mi][ni][0], acc[mi][ni][1]);
                if (r1 < Nn)
                    *(float2*)(C + (size_t)r1*Nn + col) = make_float2(acc[mi][ni][2], acc[mi][ni][3]);
            }
        }
    }
}

// ---------------- launch ----------------
extern "C" void kernel_launch(void* const* d_in, const int* in_sizes, int n_in,
                              void* d_out, int out_size){
    const float*     x   = (const float*)d_in[0];
    const void*      ei  = d_in[1];
    const float*     ea  = (const float*)d_in[2];
    const float*     W1  = (const float*)d_in[3];
    const float*     as1 = (const float*)d_in[4];
    const float*     ad1 = (const float*)d_in[5];
    const float*     We1 = (const float*)d_in[6];
    const float*     ae1 = (const float*)d_in[7];
    const float*     b1  = (const float*)d_in[8];
    const float*     W2  = (const float*)d_in[9];
    const float*     as2 = (const float*)d_in[10];
    const float*     ad2 = (const float*)d_in[11];
    const float*     We2 = (const float*)d_in[12];
    const float*     ae2 = (const float*)d_in[13];
    const float*     b2  = (const float*)d_in[14];
    const float*     Wp  = (const float*)d_in[15];
    const float*     bp  = (const float*)d_in[16];

    int E  = in_sizes[1]/2;
    if (E > EBASE) E = EBASE;
    int ET = E + Nn;

    float* out  = (float*)d_out;
    float* Ahat = out;
    float* P    = out + (size_t)Nn*Nn;
    float* Zo   = P + (size_t)Nn*NKC;

    float *h1, *hl1, *agg1, *h2p, *agg2, *zb;
    float *pas1, *pad1, *pas2, *pad2, *den1, *den2, *ex1, *ex2;
    unsigned *m1, *m2;
    unsigned short *zA, *zB;
    cudaGetSymbolAddress((void**)&h1,   g_h1);
    cudaGetSymbolAddress((void**)&hl1,  g_hl1);
    cudaGetSymbolAddress((void**)&agg1, g_agg1);
    cudaGetSymbolAddress((void**)&h2p,  g_h2);
    cudaGetSymbolAddress((void**)&agg2, g_agg2);
    cudaGetSymbolAddress((void**)&zb,   g_z);
    cudaGetSymbolAddress((void**)&pas1, g_as1);
    cudaGetSymbolAddress((void**)&pad1, g_ad1);
    cudaGetSymbolAddress((void**)&pas2, g_as2);
    cudaGetSymbolAddress((void**)&pad2, g_ad2);
    cudaGetSymbolAddress((void**)&den1, g_den1);
    cudaGetSymbolAddress((void**)&den2, g_den2);
    cudaGetSymbolAddress((void**)&ex1,  g_ex1);
    cudaGetSymbolAddress((void**)&ex2,  g_ex2);
    cudaGetSymbolAddress((void**)&m1,   g_m1);
    cudaGetSymbolAddress((void**)&m2,   g_m2);
    cudaGetSymbolAddress((void**)&zA,   g_zA);
    cudaGetSymbolAddress((void**)&zB,   g_zB);

    k_detect<<<1, 32>>>((const unsigned*)ei);
    k_convert<<<(2*E + 255)/256, 256>>>(ei, 2*E);
    k_ae<<<1, 32>>>(We1, ae1, We2, ae2);

    // -------- layer 1 --------
    gemm64<true><<<dim3(HC1/64, (Nn+63)/64), 256>>>(x, W1, h1, Nn, HC1, INC);
    k_attn<<<(Nn*NH*32 + 255)/256, 256>>>(h1, as1, ad1, pas1, pad1, HIDC);

    k_zero<<<(Nn*NH + 255)/256, 256>>>((float*)m1, Nn*NH);
    k_zero<<<(Nn*NH + 255)/256, 256>>>(den1, Nn*NH);
    k_zero<<<(Nn*HC1 + 255)/256, 256>>>(agg1, Nn*HC1);

    k_edge_max<<<(ET + 255)/256, 256>>>(ea, pas1, pad1, m1, E, 0);
    k_edge_exp<<<(ET + 255)/256, 256>>>(ea, pas1, pad1, m1, ex1, den1, E, 0);
    k_coef<<<(ET*NH + 255)/256, 256>>>(den1, ex1, E);
    k_scatter<HIDC><<<ET, NH*HIDC>>>(h1, ex1, agg1, E);
    k_biasact<<<(Nn*HC1 + 255)/256, 256>>>(agg1, b1, hl1, Nn*HC1, HC1, 1);

    // -------- layer 2 --------
    gemm64<false><<<dim3(HC2/64, (Nn+63)/64), 256>>>(hl1, W2, h2p, Nn, HC2, HC1);
    k_attn<<<(Nn*NH*32 + 255)/256, 256>>>(h2p, as2, ad2, pas2, pad2, OUTC);

    k_zero<<<(Nn*NH + 255)/256, 256>>>((float*)m2, Nn*NH);
    k_zero<<<(Nn*NH + 255)/256, 256>>>(den2, Nn*NH);
    k_zero<<<(Nn*HC2 + 255)/256, 256>>>(agg2, Nn*HC2);

    k_edge_max<<<(ET + 255)/256, 256>>>(ea, pas2, pad2, m2, E, NH);
    k_edge_exp<<<(ET + 255)/256, 256>>>(ea, pas2, pad2, m2, ex2, den2, E, NH);
    k_coef<<<(ET*NH + 255)/256, 256>>>(den2, ex2, E);
    k_scatter<OUTC><<<ET, NH*OUTC>>>(h2p, ex2, agg2, E);
    k_biasact<<<(Nn*HC2 + 255)/256, 256>>>(agg2, b2, h2p, Nn*HC2, HC2, 0);

    // -------- head --------
    k_norm<<<(Nn*32 + 255)/256, 256>>>(h2p, zb, Zo);
    k_p<<<(Nn + 255)/256, 256>>>(zb, Wp, bp, P);
    k_pack<<<(MPAD*HC2 + 255)/256, 256>>>(zb, zA, zB);

    const int SYRK_SMEM = 2*BUFB;   // 73728 B
    cudaFuncSetAttribute(k_syrk_mma, cudaFuncAttributeMaxDynamicSharedMemorySize, SYRK_SMEM);
    k_syrk_mma<<<dim3(MPAD/128, MPAD/128), 256, SYRK_SMEM>>>((const char*)zA, (const char*)zB, Ahat);
}

// round 8
// speedup vs baseline: 2.1531x; 1.4416x over previous
#include <cuda_runtime.h>
#include <cuda_bf16.h>
#include <stdint.h>
#include <math.h>

#define Nn   10000
#define INC  128
#define HIDC 128
#define OUTC 64
#define NH   3
#define NKC  10
#define HC1  (NH*HIDC)   /* 384 */
#define HC2  (NH*OUTC)   /* 192 */
#define EBASE 320000
#define ETOTC (EBASE+Nn) /* 330000 */

#define MPAD 10112       /* 79*128 */
#define KCAT 576         /* 3*HC2 */
#define BK   64
#define NIT  (KCAT/BK)   /* 9 */
#define SROW 72          /* smem row stride in bf16 (144B): conflict-free frags */
#define TILEB (128*SROW*2)   /* 18432 B per tile */
#define BUFB  (2*TILEB)      /* 36864 B per buffer (A+B) */

// ---------------- scratch (device globals; no allocation allowed) ----------------
__device__ float    g_h1[Nn*HC1];
__device__ float    g_hl1[Nn*HC1];
__device__ float    g_h2[Nn*HC2];
__device__ float    g_z[Nn*HC2];
__device__ float    g_as1[Nn*NH], g_ad1[Nn*NH], g_as2[Nn*NH], g_ad2[Nn*NH];
__device__ unsigned g_m1[Nn*NH],  g_m2[Nn*NH];
__device__ float    g_den1[Nn*NH], g_den2[Nn*NH];
__device__ float    g_ex1[ETOTC*NH], g_ex2[ETOTC*NH];
__device__ float    g_ae[2*NH];
__device__ int      g_ei[2*EBASE];
__device__ int      g_is64;
// CSR by destination
__device__ int      g_deg[Nn];
__device__ int      g_rowptr[Nn+1];
__device__ int      g_epos[Nn];
__device__ int      g_esort[ETOTC];
__device__ int      g_ssort[ETOTC];
__device__ unsigned short g_zA[(size_t)MPAD*KCAT];   // bf16 [hi|hi|lo]
__device__ unsigned short g_zB[(size_t)MPAD*KCAT];   // bf16 [hi|lo|hi]

// order-preserving float<->uint for atomicMax over signed floats
__device__ __forceinline__ unsigned f2o(float f){
    unsigned u = __float_as_uint(f);
    return (u & 0x80000000u) ? ~u : (u | 0x80000000u);
}
__device__ __forceinline__ float o2f(unsigned u){
    return (u & 0x80000000u) ? __uint_as_float(u & 0x7fffffffu) : __uint_as_float(~u);
}

// ---------------- edge-index dtype detect + convert ----------------
__global__ void k_detect(const unsigned* __restrict__ raw){
    if (threadIdx.x == 0){
        int ok64 = 1;
        for (int i = 0; i < 64; i++)
            if (raw[2*i+1] != 0u){ ok64 = 0; break; }
        g_is64 = ok64;
    }
}
__global__ void k_convert(const void* __restrict__ raw, int n){
    int i = blockIdx.x*blockDim.x + threadIdx.x;
    if (i >= n) return;
    if (g_is64) g_ei[i] = (int)((const long long*)raw)[i];
    else        g_ei[i] = ((const int*)raw)[i];
}

// ---------------- CSR build ----------------
__global__ void k_hist(int E){
    int e = blockIdx.x*blockDim.x + threadIdx.x;
    if (e >= E + Nn) return;
    int d = (e < E) ? g_ei[E+e] : (e - E);
    atomicAdd(&g_deg[d], 1);
}
#define SCT 1024
#define SCHUNK ((Nn + SCT - 1)/SCT)
__global__ void __launch_bounds__(SCT) k_scan(){
    __shared__ int part[SCT];
    int t = threadIdx.x;
    int base = t*SCHUNK;
    int s = 0;
    for (int j = 0; j < SCHUNK; j++){
        int idx = base + j;
        if (idx < Nn) s += g_deg[idx];
    }
    part[t] = s;
    __syncthreads();
    for (int off = 1; off < SCT; off <<= 1){
        int v = (t >= off) ? part[t-off] : 0;
        __syncthreads();
        part[t] += v;
        __syncthreads();
    }
    int run = (t == 0) ? 0 : part[t-1];
    for (int j = 0; j < SCHUNK; j++){
        int idx = base + j;
        if (idx < Nn){
            g_rowptr[idx] = run;
            g_epos[idx]   = run;
            run += g_deg[idx];
        }
    }
    if (t == SCT-1) g_rowptr[Nn] = run;
}
__global__ void k_fill(int E){
    int e = blockIdx.x*blockDim.x + threadIdx.x;
    if (e >= E + Nn) return;
    int s, d;
    if (e < E){ s = g_ei[e]; d = g_ei[E+e]; }
    else      { s = e - E; d = s; }
    int pos = atomicAdd(&g_epos[d], 1);
    g_esort[pos] = e;
    g_ssort[pos] = s;
}

// ---------------- misc ----------------
__global__ void k_zero(float* p, int n){
    int i = blockIdx.x*blockDim.x + threadIdx.x;
    if (i < n) p[i] = 0.f;
}

__global__ void k_ae(const float* We1, const float* ate1, const float* We2, const float* ate2){
    int t = threadIdx.x;
    if (t < NH){
        float s = 0.f;
        for (int c = 0; c < HIDC; c++) s += We1[t*HIDC+c]*ate1[t*HIDC+c];
        g_ae[t] = s;
    } else if (t < 2*NH){
        int h = t - NH; float s = 0.f;
        for (int c = 0; c < OUTC; c++) s += We2[h*OUTC+c]*ate2[h*OUTC+c];
        g_ae[NH+h] = s;
    }
}

// ---------------- generic 64x64x16 fp32 GEMM (row-major NN) ----------------
template<bool SAN>
__global__ void __launch_bounds__(256) gemm64(const float* __restrict__ A,
                                              const float* __restrict__ B,
                                              float* __restrict__ C,
                                              int M, int Ncol, int K){
    __shared__ float As[16][64];
    __shared__ float Bs[16][64];
    int rb = blockIdx.y*64, cb = blockIdx.x*64;
    int tid = threadIdx.x;
    int tx = tid & 15, ty = tid >> 4;
    float acc[4][4] = {};
    for (int k0 = 0; k0 < K; k0 += 16){
        {
            int r = tid >> 2, k4 = (tid & 3)*4;
            float4 v = make_float4(0.f,0.f,0.f,0.f);
            if (rb + r < M) v = *(const float4*)(A + (size_t)(rb+r)*K + k0 + k4);
            if (SAN){
                v.x = isnan(v.x)?0.f:v.x; v.y = isnan(v.y)?0.f:v.y;
                v.z = isnan(v.z)?0.f:v.z; v.w = isnan(v.w)?0.f:v.w;
            }
            As[k4+0][r]=v.x; As[k4+1][r]=v.y; As[k4+2][r]=v.z; As[k4+3][r]=v.w;
        }
        {
            int kr = tid >> 4, c4 = (tid & 15)*4;
            *(float4*)&Bs[kr][c4] = *(const float4*)(B + (size_t)(k0+kr)*Ncol + cb + c4);
        }
        __syncthreads();
        #pragma unroll
        for (int k = 0; k < 16; k++){
            float4 a4 = *(float4*)&As[k][ty*4];
            float4 b4 = *(float4*)&Bs[k][tx*4];
            float av[4] = {a4.x,a4.y,a4.z,a4.w};
            float bv[4] = {b4.x,b4.y,b4.z,b4.w};
            #pragma unroll
            for (int i = 0; i < 4; i++)
                #pragma unroll
                for (int j = 0; j < 4; j++)
                    acc[i][j] += av[i]*bv[j];
        }
        __syncthreads();
    }
    #pragma unroll
    for (int i = 0; i < 4; i++){
        int row = rb + ty*4 + i;
        if (row < M)
            *(float4*)(C + (size_t)row*Ncol + cb + tx*4) =
                make_float4(acc[i][0],acc[i][1],acc[i][2],acc[i][3]);
    }
}

// ---------------- attention logits ----------------
__global__ void k_attn(const float* __restrict__ hfeat, const float* __restrict__ atts,
                       const float* __restrict__ attd, float* __restrict__ as_,
                       float* __restrict__ ad_, int C){
    int gw   = (blockIdx.x*blockDim.x + threadIdx.x) >> 5;
    int lane = threadIdx.x & 31;
    if (gw >= Nn*NH) return;
    int n = gw / NH, hh = gw % NH;
    const float* hp = hfeat + (size_t)n*NH*C + hh*C;
    float s = 0.f, d = 0.f;
    for (int c = lane; c < C; c += 32){
        float v = hp[c];
        s += v*atts[hh*C+c];
        d += v*attd[hh*C+c];
    }
    #pragma unroll
    for (int o = 16; o; o >>= 1){
        s += __shfl_xor_sync(0xffffffffu, s, o);
        d += __shfl_xor_sync(0xffffffffu, d, o);
    }
    if (lane == 0){ as_[gw] = s; ad_[gw] = d; }
}

// ---------------- edge segment softmax ----------------
__global__ void k_edge_max(const float* __restrict__ ea,
                           const float* __restrict__ as_, const float* __restrict__ ad_,
                           unsigned* __restrict__ m, int E, int aeoff){
    int e = blockIdx.x*blockDim.x + threadIdx.x;
    if (e >= E + Nn) return;
    int s, d; float w;
    if (e < E){ s = g_ei[e]; d = g_ei[E+e]; w = ea[e]; }
    else      { s = e - E; d = s; w = 1.f; }
    #pragma unroll
    for (int h = 0; h < NH; h++){
        float a = as_[s*NH+h] + ad_[d*NH+h] + w*g_ae[aeoff+h];
        a = a > 0.f ? a : 0.2f*a;
        atomicMax(&m[d*NH+h], f2o(a));
    }
}

__global__ void k_edge_exp(const float* __restrict__ ea,
                           const float* __restrict__ as_, const float* __restrict__ ad_,
                           const unsigned* __restrict__ m, float* __restrict__ exbuf,
                           float* __restrict__ den, int E, int aeoff){
    int e = blockIdx.x*blockDim.x + threadIdx.x;
    if (e >= E + Nn) return;
    int s, d; float w;
    if (e < E){ s = g_ei[e]; d = g_ei[E+e]; w = ea[e]; }
    else      { s = e - E; d = s; w = 1.f; }
    #pragma unroll
    for (int h = 0; h < NH; h++){
        float a = as_[s*NH+h] + ad_[d*NH+h] + w*g_ae[aeoff+h];
        a = a > 0.f ? a : 0.2f*a;
        float x = __expf(a - o2f(m[d*NH+h]));
        exbuf[(size_t)e*NH+h] = x;
        atomicAdd(&den[d*NH+h], x);
    }
}

__global__ void k_coef(const float* __restrict__ den, float* __restrict__ exbuf, int E){
    int i = blockIdx.x*blockDim.x + threadIdx.x;
    if (i >= (E+Nn)*NH) return;
    int e = i / NH, h = i - e*NH;
    int d = (e < E) ? g_ei[E+e] : (e - E);
    exbuf[i] = exbuf[i] / (den[d*NH+h] + 1e-16f);
}

// ---------------- CSR gather: out[n,t] = sum_e coef[e,h]*h[src,t] + b[t] (+ELU) ----------------
template<int C, int ELU>
__global__ void k_gather(const float* __restrict__ hfeat,
                         const float* __restrict__ coef,
                         const float* __restrict__ b,
                         float* __restrict__ o){
    int n = blockIdx.x;
    int t = threadIdx.x;              // blockDim = NH*C
    int h = t / C;
    int beg = g_rowptr[n], end = g_rowptr[n+1];
    float acc = 0.f;
    for (int p = beg; p < end; p++){
        int e = g_esort[p];
        int s = g_ssort[p];
        acc += hfeat[(size_t)s*(NH*C) + t] * coef[(size_t)e*NH + h];
    }
    float v = acc + b[t];
    if (ELU) v = v > 0.f ? v : expm1f(v);
    o[(size_t)n*(NH*C) + t] = v;
}

// ---------------- L2 normalize ----------------
__global__ void k_norm(const float* __restrict__ h, float* __restrict__ z,
                       float* __restrict__ zo){
    int gw   = (blockIdx.x*blockDim.x + threadIdx.x) >> 5;
    int lane = threadIdx.x & 31;
    if (gw >= Nn) return;
    const float* r = h + (size_t)gw*HC2;
    float s = 0.f;
    for (int c = lane; c < HC2; c += 32){ float v = r[c]; s += v*v; }
    #pragma unroll
    for (int o = 16; o; o >>= 1) s += __shfl_xor_sync(0xffffffffu, s, o);
    float inv = 1.f / fmaxf(sqrtf(s), 1e-12f);
    for (int c = lane; c < HC2; c += 32){
        float v = r[c]*inv;
        z[(size_t)gw*HC2+c]  = v;
        zo[(size_t)gw*HC2+c] = v;
    }
}

// ---------------- p = softmax(z @ Wp + bp) ----------------
__global__ void k_p(const float* __restrict__ z, const float* __restrict__ Wp,
                    const float* __restrict__ bp, float* __restrict__ P){
    __shared__ float sW[HC2*NKC];
    __shared__ float sb[NKC];
    for (int i = threadIdx.x; i < HC2*NKC; i += blockDim.x) sW[i] = Wp[i];
    if (threadIdx.x < NKC) sb[threadIdx.x] = bp[threadIdx.x];
    __syncthreads();
    int n = blockIdx.x*blockDim.x + threadIdx.x;
    if (n >= Nn) return;
    float lg[NKC];
    #pragma unroll
    for (int k = 0; k < NKC; k++) lg[k] = sb[k];
    const float* zr = z + (size_t)n*HC2;
    for (int c = 0; c < HC2; c++){
        float v = zr[c];
        #pragma unroll
        for (int k = 0; k < NKC; k++) lg[k] += v*sW[c*NKC+k];
    }
    float mx = lg[0];
    #pragma unroll
    for (int k = 1; k < NKC; k++) mx = fmaxf(mx, lg[k]);
    float sum = 0.f;
    #pragma unroll
    for (int k = 0; k < NKC; k++){ lg[k] = __expf(lg[k]-mx); sum += lg[k]; }
    float inv = 1.f/sum;
    #pragma unroll
    for (int k = 0; k < NKC; k++) P[(size_t)n*NKC+k] = lg[k]*inv;
}

// ---------------- pack z into split-bf16 operands ----------------
__global__ void k_pack(const float* __restrict__ z, unsigned short* __restrict__ ZA,
                       unsigned short* __restrict__ ZB){
    int i = blockIdx.x*blockDim.x + threadIdx.x;
    if (i >= MPAD*HC2) return;
    int n = i / HC2, c = i - n*HC2;
    float v = (n < Nn) ? z[(size_t)n*HC2 + c] : 0.f;
    __nv_bfloat16 hib = __float2bfloat16(v);
    float hif = __bfloat162float(hib);
    __nv_bfloat16 lob = __float2bfloat16(v - hif);
    unsigned short hi = __bfloat16_as_ushort(hib);
    unsigned short lo = __bfloat16_as_ushort(lob);
    size_t base = (size_t)n*KCAT + c;
    ZA[base]         = hi;
    ZA[base + HC2]   = hi;
    ZA[base + 2*HC2] = lo;
    ZB[base]         = hi;
    ZB[base + HC2]   = lo;
    ZB[base + 2*HC2] = hi;
}

// ---------------- helpers ----------------
__device__ __forceinline__ uint32_t smem_u32(const void* p){
    uint32_t a;
    asm("{ .reg .u64 t; cvta.to.shared.u64 t, %1; cvt.u32.u64 %0, t; }" : "=r"(a) : "l"(p));
    return a;
}
__device__ __forceinline__ void cpasync16(uint32_t dst, const void* src){
    asm volatile("cp.async.cg.shared.global [%0], [%1], 16;" :: "r"(dst), "l"(src));
}
__device__ __forceinline__ void cp_commit(){
    asm volatile("cp.async.commit_group;");
}
template<int N>
__device__ __forceinline__ void cp_wait(){
    asm volatile("cp.async.wait_group %0;" :: "n"(N));
}
__device__ __forceinline__ void mma16816(float* c, const uint32_t* a, const uint32_t* b){
    asm volatile(
        "mma.sync.aligned.m16n8k16.row.col.f32.bf16.bf16.f32 "
        "{%0,%1,%2,%3}, {%4,%5,%6,%7}, {%8,%9}, {%0,%1,%2,%3};"
        : "+f"(c[0]), "+f"(c[1]), "+f"(c[2]), "+f"(c[3])
        : "r"(a[0]), "r"(a[1]), "r"(a[2]), "r"(a[3]), "r"(b[0]), "r"(b[1]));
}

// async-load one 128xBK tile pair (A rows rb.., B rows cb..) for k-chunk kc
__device__ __forceinline__ void tile_load(const char* __restrict__ GA,
                                          const char* __restrict__ GB,
                                          uint32_t sA, uint32_t sB,
                                          int rb, int cb, int kc, int tid){
    #pragma unroll
    for (int i = 0; i < 4; i++){
        int chunk = tid + i*256;          // 1024 chunks of 16B per tile
        int row = chunk >> 3, seg = chunk & 7;
        size_t gofs = ((size_t)KCAT*row + kc*BK + seg*8) * 2;
        cpasync16(sA + row*(SROW*2) + seg*16, GA + (size_t)(rb)*KCAT*2 + gofs);
        cpasync16(sB + row*(SROW*2) + seg*16, GB + (size_t)(cb)*KCAT*2 + gofs);
    }
}

// ---------------- A_hat = zA zB^T via mma.sync bf16, fp32 accum ----------------
__global__ void __launch_bounds__(256) k_syrk_mma(const char* __restrict__ ZA,
                                                  const char* __restrict__ ZB,
                                                  float* __restrict__ C){
    extern __shared__ char dsm[];
    uint32_t s0 = smem_u32(dsm);

    int tid  = threadIdx.x;
    int wid  = tid >> 5, lane = tid & 31;
    int gid  = lane >> 2, tig = lane & 3;
    int mwarp = (wid & 1) * 64;       // 2 warp-rows
    int nwarp = (wid >> 1) * 32;      // 4 warp-cols
    int rb = blockIdx.y * 128, cb = blockIdx.x * 128;

    float acc[4][4][4];
    #pragma unroll
    for (int a = 0; a < 4; a++)
        #pragma unroll
        for (int b = 0; b < 4; b++)
            #pragma unroll
            for (int c = 0; c < 4; c++) acc[a][b][c] = 0.f;

    tile_load(ZA, ZB, s0, s0 + TILEB, rb, cb, 0, tid);
    cp_commit();

    for (int it = 0; it < NIT; it++){
        int s = it & 1;
        if (it + 1 < NIT){
            int ns = (it + 1) & 1;
            tile_load(ZA, ZB, s0 + ns*BUFB, s0 + ns*BUFB + TILEB, rb, cb, it + 1, tid);
            cp_commit();
            cp_wait<1>();
        } else {
            cp_wait<0>();
        }
        __syncthreads();

        const uint32_t* As32 = (const uint32_t*)(dsm + s*BUFB);
        const uint32_t* Bs32 = (const uint32_t*)(dsm + s*BUFB + TILEB);

        #pragma unroll
        for (int kk = 0; kk < BK/16; kk++){
            uint32_t af[4][4];
            #pragma unroll
            for (int mi = 0; mi < 4; mi++){
                const uint32_t* base = As32 + (size_t)(mwarp + mi*16 + gid)*(SROW/2) + tig + kk*8;
                af[mi][0] = base[0];
                af[mi][1] = base[8*(SROW/2)];
                af[mi][2] = base[4];
                af[mi][3] = base[8*(SROW/2) + 4];
            }
            uint32_t bf[4][2];
            #pragma unroll
            for (int ni = 0; ni < 4; ni++){
                const uint32_t* bb = Bs32 + (size_t)(nwarp + ni*8 + gid)*(SROW/2) + tig + kk*8;
                bf[ni][0] = bb[0];
                bf[ni][1] = bb[4];
            }
            #pragma unroll
            for (int mi = 0; mi < 4; mi++)
                #pragma unroll
                for (int ni = 0; ni < 4; ni++)
                    mma16816(acc[mi][ni], af[mi], bf[ni]);
        }
        __syncthreads();
    }

    // epilogue: documented c-frag layout
    #pragma unroll
    for (int mi = 0; mi < 4; mi++){
        int r0 = rb + mwarp + mi*16 + gid;
        int r1 = r0 + 8;
        #pragma unroll
        for (int ni = 0; ni < 4; ni++){
            int col = cb + nwarp + ni*8 + tig*2;
            if (col + 1 < Nn){
                if (r0 < Nn)
                    *(float2*)(C + (size_t)r0*Nn + col) = make_float2(acc[mi][ni][0], acc[mi][ni][1]);
                if (r1 < Nn)
                    *(float2*)(C + (size_t)r1*Nn + col) = make_float2(acc[mi][ni][2], acc[mi][ni][3]);
            }
        }
    }
}

// ---------------- launch ----------------
extern "C" void kernel_launch(void* const* d_in, const int* in_sizes, int n_in,
                              void* d_out, int out_size){
    const float*     x   = (const float*)d_in[0];
    const void*      ei  = d_in[1];
    const float*     ea  = (const float*)d_in[2];
    const float*     W1  = (const float*)d_in[3];
    const float*     as1 = (const float*)d_in[4];
    const float*     ad1 = (const float*)d_in[5];
    const float*     We1 = (const float*)d_in[6];
    const float*     ae1 = (const float*)d_in[7];
    const float*     b1  = (const float*)d_in[8];
    const float*     W2  = (const float*)d_in[9];
    const float*     as2 = (const float*)d_in[10];
    const float*     ad2 = (const float*)d_in[11];
    const float*     We2 = (const float*)d_in[12];
    const float*     ae2 = (const float*)d_in[13];
    const float*     b2  = (const float*)d_in[14];
    const float*     Wp  = (const float*)d_in[15];
    const float*     bp  = (const float*)d_in[16];

    int E  = in_sizes[1]/2;
    if (E > EBASE) E = EBASE;
    int ET = E + Nn;

    float* out  = (float*)d_out;
    float* Ahat = out;
    float* P    = out + (size_t)Nn*Nn;
    float* Zo   = P + (size_t)Nn*NKC;

    float *h1, *hl1, *h2p, *zb;
    float *pas1, *pad1, *pas2, *pad2, *den1, *den2, *ex1, *ex2;
    unsigned *m1, *m2;
    unsigned short *zA, *zB;
    int *degp;
    cudaGetSymbolAddress((void**)&h1,   g_h1);
    cudaGetSymbolAddress((void**)&hl1,  g_hl1);
    cudaGetSymbolAddress((void**)&h2p,  g_h2);
    cudaGetSymbolAddress((void**)&zb,   g_z);
    cudaGetSymbolAddress((void**)&pas1, g_as1);
    cudaGetSymbolAddress((void**)&pad1, g_ad1);
    cudaGetSymbolAddress((void**)&pas2, g_as2);
    cudaGetSymbolAddress((void**)&pad2, g_ad2);
    cudaGetSymbolAddress((void**)&den1, g_den1);
    cudaGetSymbolAddress((void**)&den2, g_den2);
    cudaGetSymbolAddress((void**)&ex1,  g_ex1);
    cudaGetSymbolAddress((void**)&ex2,  g_ex2);
    cudaGetSymbolAddress((void**)&m1,   g_m1);
    cudaGetSymbolAddress((void**)&m2,   g_m2);
    cudaGetSymbolAddress((void**)&zA,   g_zA);
    cudaGetSymbolAddress((void**)&zB,   g_zB);
    cudaGetSymbolAddress((void**)&degp, g_deg);

    k_detect<<<1, 32>>>((const unsigned*)ei);
    k_convert<<<(2*E + 255)/256, 256>>>(ei, 2*E);
    k_ae<<<1, 32>>>(We1, ae1, We2, ae2);

    // -------- CSR build (once; shared by both layers) --------
    k_zero<<<(Nn + 255)/256, 256>>>((float*)degp, Nn);
    k_hist<<<(ET + 255)/256, 256>>>(E);
    k_scan<<<1, SCT>>>();
    k_fill<<<(ET + 255)/256, 256>>>(E);

    // -------- layer 1 --------
    gemm64<true><<<dim3(HC1/64, (Nn+63)/64), 256>>>(x, W1, h1, Nn, HC1, INC);
    k_attn<<<(Nn*NH*32 + 255)/256, 256>>>(h1, as1, ad1, pas1, pad1, HIDC);

    k_zero<<<(Nn*NH + 255)/256, 256>>>((float*)m1, Nn*NH);
    k_zero<<<(Nn*NH + 255)/256, 256>>>(den1, Nn*NH);

    k_edge_max<<<(ET + 255)/256, 256>>>(ea, pas1, pad1, m1, E, 0);
    k_edge_exp<<<(ET + 255)/256, 256>>>(ea, pas1, pad1, m1, ex1, den1, E, 0);
    k_coef<<<(ET*NH + 255)/256, 256>>>(den1, ex1, E);
    k_gather<HIDC,1><<<Nn, NH*HIDC>>>(h1, ex1, b1, hl1);

    // -------- layer 2 --------
    gemm64<false><<<dim3(HC2/64, (Nn+63)/64), 256>>>(hl1, W2, h2p, Nn, HC2, HC1);
    k_attn<<<(Nn*NH*32 + 255)/256, 256>>>(h2p, as2, ad2, pas2, pad2, OUTC);

    k_zero<<<(Nn*NH + 255)/256, 256>>>((float*)m2, Nn*NH);
    k_zero<<<(Nn*NH + 255)/256, 256>>>(den2, Nn*NH);

    k_edge_max<<<(ET + 255)/256, 256>>>(ea, pas2, pad2, m2, E, NH);
    k_edge_exp<<<(ET + 255)/256, 256>>>(ea, pas2, pad2, m2, ex2, den2, E, NH);
    k_coef<<<(ET*NH + 255)/256, 256>>>(den2, ex2, E);
    k_gather<OUTC,0><<<Nn, NH*OUTC>>>(h2p, ex2, b2, hl1);   // output -> hl1 (h2p stays intact as source)

    // -------- head --------
    k_norm<<<(Nn*32 + 255)/256, 256>>>(hl1, zb, Zo);
    k_p<<<(Nn + 255)/256, 256>>>(zb, Wp, bp, P);
    k_pack<<<(MPAD*HC2 + 255)/256, 256>>>(zb, zA, zB);

    const int SYRK_SMEM = 2*BUFB;   // 73728 B
    cudaFuncSetAttribute(k_syrk_mma, cudaFuncAttributeMaxDynamicSharedMemorySize, SYRK_SMEM);
    k_syrk_mma<<<dim3(MPAD/128, MPAD/128), 256, SYRK_SMEM>>>((const char*)zA, (const char*)zB, Ahat);
}

// round 9
// speedup vs baseline: 2.8947x; 1.3444x over previous
#include <cuda_runtime.h>
#include <cuda_bf16.h>
#include <stdint.h>
#include <math.h>

#define Nn   10000
#define INC  128
#define HIDC 128
#define OUTC 64
#define NH   3
#define NKC  10
#define HC1  (NH*HIDC)   /* 384 */
#define HC2  (NH*OUTC)   /* 192 */
#define EBASE 320000
#define ETOTC (EBASE+Nn) /* 330000 */

#define MPAD 10112       /* 79*128 */
#define NTILE 79
#define NTRI  (NTILE*(NTILE+1)/2)   /* 3160 */
#define KCAT 576         /* 3*HC2 */
#define BK   64
#define NIT  (KCAT/BK)   /* 9 */
#define SROW 72          /* smem row stride in bf16 (144B): conflict-free frags */
#define TILEB (128*SROW*2)   /* 18432 B per tile */
#define BUFB  (2*TILEB)      /* 36864 B per buffer (A+B) */

// ---------------- scratch (device globals; no allocation allowed) ----------------
__device__ float    g_h1[Nn*HC1];
__device__ float    g_hl1[Nn*HC1];
__device__ float    g_h2[Nn*HC2];
__device__ float    g_z[Nn*HC2];
__device__ float    g_as1[Nn*NH], g_ad1[Nn*NH], g_as2[Nn*NH], g_ad2[Nn*NH];
__device__ float    g_den1[Nn*NH], g_den2[Nn*NH];
__device__ float    g_ex1[ETOTC*NH], g_ex2[ETOTC*NH];
__device__ float    g_ae[2*NH];
__device__ int      g_ei[2*EBASE];
__device__ int      g_is64;
// CSR by destination
__device__ int      g_deg[Nn];
__device__ int      g_rowptr[Nn+1];
__device__ int      g_epos[Nn];
__device__ int      g_esort[ETOTC];
__device__ int      g_ssort[ETOTC];
__device__ unsigned short g_zA[(size_t)MPAD*KCAT];   // bf16 [hi|hi|lo]
__device__ unsigned short g_zB[(size_t)MPAD*KCAT];   // bf16 [hi|lo|hi]

// ---------------- edge-index dtype detect + convert ----------------
__global__ void k_detect(const unsigned* __restrict__ raw){
    if (threadIdx.x == 0){
        int ok64 = 1;
        for (int i = 0; i < 64; i++)
            if (raw[2*i+1] != 0u){ ok64 = 0; break; }
        g_is64 = ok64;
    }
}
__global__ void k_convert(const void* __restrict__ raw, int n){
    int i = blockIdx.x*blockDim.x + threadIdx.x;
    if (i >= n) return;
    if (g_is64) g_ei[i] = (int)((const long long*)raw)[i];
    else        g_ei[i] = ((const int*)raw)[i];
}

// ---------------- CSR build ----------------
__global__ void k_hist(int E){
    int e = blockIdx.x*blockDim.x + threadIdx.x;
    if (e >= E + Nn) return;
    int d = (e < E) ? g_ei[E+e] : (e - E);
    atomicAdd(&g_deg[d], 1);
}
#define SCT 1024
#define SCHUNK ((Nn + SCT - 1)/SCT)
__global__ void __launch_bounds__(SCT) k_scan(){
    __shared__ int part[SCT];
    int t = threadIdx.x;
    int base = t*SCHUNK;
    int s = 0;
    for (int j = 0; j < SCHUNK; j++){
        int idx = base + j;
        if (idx < Nn) s += g_deg[idx];
    }
    part[t] = s;
    __syncthreads();
    for (int off = 1; off < SCT; off <<= 1){
        int v = (t >= off) ? part[t-off] : 0;
        __syncthreads();
        part[t] += v;
        __syncthreads();
    }
    int run = (t == 0) ? 0 : part[t-1];
    for (int j = 0; j < SCHUNK; j++){
        int idx = base + j;
        if (idx < Nn){
            g_rowptr[idx] = run;
            g_epos[idx]   = run;
            run += g_deg[idx];
        }
    }
    if (t == SCT-1) g_rowptr[Nn] = run;
}
__global__ void k_fill(int E){
    int e = blockIdx.x*blockDim.x + threadIdx.x;
    if (e >= E + Nn) return;
    int s, d;
    if (e < E){ s = g_ei[e]; d = g_ei[E+e]; }
    else      { s = e - E; d = s; }
    int pos = atomicAdd(&g_epos[d], 1);
    g_esort[pos] = e;
    g_ssort[pos] = s;
}

// ---------------- misc ----------------
__global__ void k_zero(float* p, int n){
    int i = blockIdx.x*blockDim.x + threadIdx.x;
    if (i < n) p[i] = 0.f;
}

__global__ void k_ae(const float* We1, const float* ate1, const float* We2, const float* ate2){
    int t = threadIdx.x;
    if (t < NH){
        float s = 0.f;
        for (int c = 0; c < HIDC; c++) s += We1[t*HIDC+c]*ate1[t*HIDC+c];
        g_ae[t] = s;
    } else if (t < 2*NH){
        int h = t - NH; float s = 0.f;
        for (int c = 0; c < OUTC; c++) s += We2[h*OUTC+c]*ate2[h*OUTC+c];
        g_ae[NH+h] = s;
    }
}

// ---------------- generic 64x64x16 fp32 GEMM (row-major NN) ----------------
template<bool SAN>
__global__ void __launch_bounds__(256) gemm64(const float* __restrict__ A,
                                              const float* __restrict__ B,
                                              float* __restrict__ C,
                                              int M, int Ncol, int K){
    __shared__ float As[16][64];
    __shared__ float Bs[16][64];
    int rb = blockIdx.y*64, cb = blockIdx.x*64;
    int tid = threadIdx.x;
    int tx = tid & 15, ty = tid >> 4;
    float acc[4][4] = {};
    for (int k0 = 0; k0 < K; k0 += 16){
        {
            int r = tid >> 2, k4 = (tid & 3)*4;
            float4 v = make_float4(0.f,0.f,0.f,0.f);
            if (rb + r < M) v = *(const float4*)(A + (size_t)(rb+r)*K + k0 + k4);
            if (SAN){
                v.x = isnan(v.x)?0.f:v.x; v.y = isnan(v.y)?0.f:v.y;
                v.z = isnan(v.z)?0.f:v.z; v.w = isnan(v.w)?0.f:v.w;
            }
            As[k4+0][r]=v.x; As[k4+1][r]=v.y; As[k4+2][r]=v.z; As[k4+3][r]=v.w;
        }
        {
            int kr = tid >> 4, c4 = (tid & 15)*4;
            *(float4*)&Bs[kr][c4] = *(const float4*)(B + (size_t)(k0+kr)*Ncol + cb + c4);
        }
        __syncthreads();
        #pragma unroll
        for (int k = 0; k < 16; k++){
            float4 a4 = *(float4*)&As[k][ty*4];
            float4 b4 = *(float4*)&Bs[k][tx*4];
            float av[4] = {a4.x,a4.y,a4.z,a4.w};
            float bv[4] = {b4.x,b4.y,b4.z,b4.w};
            #pragma unroll
            for (int i = 0; i < 4; i++)
                #pragma unroll
                for (int j = 0; j < 4; j++)
                    acc[i][j] += av[i]*bv[j];
        }
        __syncthreads();
    }
    #pragma unroll
    for (int i = 0; i < 4; i++){
        int row = rb + ty*4 + i;
        if (row < M)
            *(float4*)(C + (size_t)row*Ncol + cb + tx*4) =
                make_float4(acc[i][0],acc[i][1],acc[i][2],acc[i][3]);
    }
}

// ---------------- attention logits ----------------
__global__ void k_attn(const float* __restrict__ hfeat, const float* __restrict__ atts,
                       const float* __restrict__ attd, float* __restrict__ as_,
                       float* __restrict__ ad_, int C){
    int gw   = (blockIdx.x*blockDim.x + threadIdx.x) >> 5;
    int lane = threadIdx.x & 31;
    if (gw >= Nn*NH) return;
    int n = gw / NH, hh = gw % NH;
    const float* hp = hfeat + (size_t)n*NH*C + hh*C;
    float s = 0.f, d = 0.f;
    for (int c = lane; c < C; c += 32){
        float v = hp[c];
        s += v*atts[hh*C+c];
        d += v*attd[hh*C+c];
    }
    #pragma unroll
    for (int o = 16; o; o >>= 1){
        s += __shfl_xor_sync(0xffffffffu, s, o);
        d += __shfl_xor_sync(0xffffffffu, d, o);
    }
    if (lane == 0){ as_[gw] = s; ad_[gw] = d; }
}

// ---------------- edge exp (no max shift: coefs are shift-invariant) ----------------
__global__ void k_edge_exp(const float* __restrict__ ea,
                           const float* __restrict__ as_, const float* __restrict__ ad_,
                           float* __restrict__ exbuf, float* __restrict__ den,
                           int E, int aeoff){
    int e = blockIdx.x*blockDim.x + threadIdx.x;
    if (e >= E + Nn) return;
    int s, d; float w;
    if (e < E){ s = g_ei[e]; d = g_ei[E+e]; w = ea[e]; }
    else      { s = e - E; d = s; w = 1.f; }
    #pragma unroll
    for (int h = 0; h < NH; h++){
        float a = as_[s*NH+h] + ad_[d*NH+h] + w*g_ae[aeoff+h];
        a = a > 0.f ? a : 0.2f*a;
        float x = __expf(a);
        exbuf[(size_t)e*NH+h] = x;
        atomicAdd(&den[d*NH+h], x);
    }
}

// ---------------- CSR gather with fused normalization + bias (+ELU) ----------------
// out[n,t] = (sum_e ex[e,h]*h[src,t]) / den[n,h] + b[t]
template<int C, int ELU>
__global__ void k_gather(const float* __restrict__ hfeat,
                         const float* __restrict__ exbuf,
                         const float* __restrict__ den,
                         const float* __restrict__ b,
                         float* __restrict__ o){
    int n = blockIdx.x;
    int t = threadIdx.x;              // blockDim = NH*C
    int h = t / C;
    float invd = 1.f / (den[n*NH + h] + 1e-16f);
    int beg = g_rowptr[n], end = g_rowptr[n+1];
    float acc = 0.f;
    for (int p = beg; p < end; p++){
        int e = g_esort[p];
        int s = g_ssort[p];
        acc += hfeat[(size_t)s*(NH*C) + t] * exbuf[(size_t)e*NH + h];
    }
    float v = acc*invd + b[t];
    if (ELU) v = v > 0.f ? v : expm1f(v);
    o[(size_t)n*(NH*C) + t] = v;
}

// ---------------- L2 normalize ----------------
__global__ void k_norm(const float* __restrict__ h, float* __restrict__ z,
                       float* __restrict__ zo){
    int gw   = (blockIdx.x*blockDim.x + threadIdx.x) >> 5;
    int lane = threadIdx.x & 31;
    if (gw >= Nn) return;
    const float* r = h + (size_t)gw*HC2;
    float s = 0.f;
    for (int c = lane; c < HC2; c += 32){ float v = r[c]; s += v*v; }
    #pragma unroll
    for (int o = 16; o; o >>= 1) s += __shfl_xor_sync(0xffffffffu, s, o);
    float inv = 1.f / fmaxf(sqrtf(s), 1e-12f);
    for (int c = lane; c < HC2; c += 32){
        float v = r[c]*inv;
        z[(size_t)gw*HC2+c]  = v;
        zo[(size_t)gw*HC2+c] = v;
    }
}

// ---------------- p = softmax(z @ Wp + bp) ----------------
__global__ void k_p(const float* __restrict__ z, const float* __restrict__ Wp,
                    const float* __restrict__ bp, float* __restrict__ P){
    __shared__ float sW[HC2*NKC];
    __shared__ float sb[NKC];
    for (int i = threadIdx.x; i < HC2*NKC; i += blockDim.x) sW[i] = Wp[i];
    if (threadIdx.x < NKC) sb[threadIdx.x] = bp[threadIdx.x];
    __syncthreads();
    int n = blockIdx.x*blockDim.x + threadIdx.x;
    if (n >= Nn) return;
    float lg[NKC];
    #pragma unroll
    for (int k = 0; k < NKC; k++) lg[k] = sb[k];
    const float* zr = z + (size_t)n*HC2;
    for (int c = 0; c < HC2; c++){
        float v = zr[c];
        #pragma unroll
        for (int k = 0; k < NKC; k++) lg[k] += v*sW[c*NKC+k];
    }
    float mx = lg[0];
    #pragma unroll
    for (int k = 1; k < NKC; k++) mx = fmaxf(mx, lg[k]);
    float sum = 0.f;
    #pragma unroll
    for (int k = 0; k < NKC; k++){ lg[k] = __expf(lg[k]-mx); sum += lg[k]; }
    float inv = 1.f/sum;
    #pragma unroll
    for (int k = 0; k < NKC; k++) P[(size_t)n*NKC+k] = lg[k]*inv;
}

// ---------------- pack z into split-bf16 operands ----------------
__global__ void k_pack(const float* __restrict__ z, unsigned short* __restrict__ ZA,
                       unsigned short* __restrict__ ZB){
    int i = blockIdx.x*blockDim.x + threadIdx.x;
    if (i >= MPAD*HC2) return;
    int n = i / HC2, c = i - n*HC2;
    float v = (n < Nn) ? z[(size_t)n*HC2 + c] : 0.f;
    __nv_bfloat16 hib = __float2bfloat16(v);
    float hif = __bfloat162float(hib);
    __nv_bfloat16 lob = __float2bfloat16(v - hif);
    unsigned short hi = __bfloat16_as_ushort(hib);
    unsigned short lo = __bfloat16_as_ushort(lob);
    size_t base = (size_t)n*KCAT + c;
    ZA[base]         = hi;
    ZA[base + HC2]   = hi;
    ZA[base + 2*HC2] = lo;
    ZB[base]         = hi;
    ZB[base + HC2]   = lo;
    ZB[base + 2*HC2] = hi;
}

// ---------------- helpers ----------------
__device__ __forceinline__ uint32_t smem_u32(const void* p){
    uint32_t a;
    asm("{ .reg .u64 t; cvta.to.shared.u64 t, %1; cvt.u32.u64 %0, t; }" : "=r"(a) : "l"(p));
    return a;
}
__device__ __forceinline__ void cpasync16(uint32_t dst, const void* src){
    asm volatile("cp.async.cg.shared.global [%0], [%1], 16;" :: "r"(dst), "l"(src));
}
__device__ __forceinline__ void cp_commit(){
    asm volatile("cp.async.commit_group;");
}
template<int N>
__device__ __forceinline__ void cp_wait(){
    asm volatile("cp.async.wait_group %0;" :: "n"(N));
}
__device__ __forceinline__ void mma16816(float* c, const uint32_t* a, const uint32_t* b){
    asm volatile(
        "mma.sync.aligned.m16n8k16.row.col.f32.bf16.bf16.f32 "
        "{%0,%1,%2,%3}, {%4,%5,%6,%7}, {%8,%9}, {%0,%1,%2,%3};"
        : "+f"(c[0]), "+f"(c[1]), "+f"(c[2]), "+f"(c[3])
        : "r"(a[0]), "r"(a[1]), "r"(a[2]), "r"(a[3]), "r"(b[0]), "r"(b[1]));
}

// async-load one 128xBK tile pair (A rows rb.., B rows cb..) for k-chunk kc
__device__ __forceinline__ void tile_load(const char* __restrict__ GA,
                                          const char* __restrict__ GB,
                                          uint32_t sA, uint32_t sB,
                                          int rb, int cb, int kc, int tid){
    #pragma unroll
    for (int i = 0; i < 4; i++){
        int chunk = tid + i*256;          // 1024 chunks of 16B per tile
        int row = chunk >> 3, seg = chunk & 7;
        size_t gofs = ((size_t)KCAT*row + kc*BK + seg*8) * 2;
        cpasync16(sA + row*(SROW*2) + seg*16, GA + (size_t)(rb)*KCAT*2 + gofs);
        cpasync16(sB + row*(SROW*2) + seg*16, GB + (size_t)(cb)*KCAT*2 + gofs);
    }
}

// ---------------- A_hat = zA zB^T, upper-triangular tiles + mirror ----------------
__global__ void __launch_bounds__(256) k_syrk_mma(const char* __restrict__ ZA,
                                                  const char* __restrict__ ZB,
                                                  float* __restrict__ C){
    extern __shared__ char dsm[];
    uint32_t s0 = smem_u32(dsm);

    int tid  = threadIdx.x;
    int wid  = tid >> 5, lane = tid & 31;
    int gid  = lane >> 2, tig = lane & 3;
    int mwarp = (wid & 1) * 64;       // 2 warp-rows
    int nwarp = (wid >> 1) * 32;      // 4 warp-cols

    // decode upper-triangular tile (i <= j) from linear block id
    int ti = 0, rem = blockIdx.x;
    while (rem >= NTILE - ti){ rem -= NTILE - ti; ti++; }
    int tj = ti + rem;
    int rb = ti * 128, cb = tj * 128;

    float acc[4][4][4];
    #pragma unroll
    for (int a = 0; a < 4; a++)
        #pragma unroll
        for (int b = 0; b < 4; b++)
            #pragma unroll
            for (int c = 0; c < 4; c++) acc[a][b][c] = 0.f;

    tile_load(ZA, ZB, s0, s0 + TILEB, rb, cb, 0, tid);
    cp_commit();

    for (int it = 0; it < NIT; it++){
        int s = it & 1;
        if (it + 1 < NIT){
            int ns = (it + 1) & 1;
            tile_load(ZA, ZB, s0 + ns*BUFB, s0 + ns*BUFB + TILEB, rb, cb, it + 1, tid);
            cp_commit();
            cp_wait<1>();
        } else {
            cp_wait<0>();
        }
        __syncthreads();

        const uint32_t* As32 = (const uint32_t*)(dsm + s*BUFB);
        const uint32_t* Bs32 = (const uint32_t*)(dsm + s*BUFB + TILEB);

        #pragma unroll
        for (int kk = 0; kk < BK/16; kk++){
            uint32_t af[4][4];
            #pragma unroll
            for (int mi = 0; mi < 4; mi++){
                const uint32_t* base = As32 + (size_t)(mwarp + mi*16 + gid)*(SROW/2) + tig + kk*8;
                af[mi][0] = base[0];
                af[mi][1] = base[8*(SROW/2)];
                af[mi][2] = base[4];
                af[mi][3] = base[8*(SROW/2) + 4];
            }
            uint32_t bf[4][2];
            #pragma unroll
            for (int ni = 0; ni < 4; ni++){
                const uint32_t* bb = Bs32 + (size_t)(nwarp + ni*8 + gid)*(SROW/2) + tig + kk*8;
                bf[ni][0] = bb[0];
                bf[ni][1] = bb[4];
            }
            #pragma unroll
            for (int mi = 0; mi < 4; mi++)
                #pragma unroll
                for (int ni = 0; ni < 4; ni++)
                    mma16816(acc[mi][ni], af[mi], bf[ni]);
        }
        __syncthreads();
    }

    // direct write (rows rb.., cols cb..)
    #pragma unroll
    for (int mi = 0; mi < 4; mi++){
        int r0 = rb + mwarp + mi*16 + gid;
        int r1 = r0 + 8;
        #pragma unroll
        for (int ni = 0; ni < 4; ni++){
            int col = cb + nwarp + ni*8 + tig*2;
            if (col + 1 < Nn){
                if (r0 < Nn)
                    *(float2*)(C + (size_t)r0*Nn + col) = make_float2(acc[mi][ni][0], acc[mi][ni][1]);
                if (r1 < Nn)
                    *(float2*)(C + (size_t)r1*Nn + col) = make_float2(acc[mi][ni][2], acc[mi][ni][3]);
            }
        }
    }

    // mirror write for off-diagonal tiles: C[cb+c, rb+r] = tile[r][c]
    if (ti != tj){
        float* st = (float*)dsm;          // 128 x 128, stride 129 (conflict-free transpose read)
        __syncthreads();                  // mainloop smem no longer needed
        #pragma unroll
        for (int mi = 0; mi < 4; mi++){
            int r0 = mwarp + mi*16 + gid;
            int r1 = r0 + 8;
            #pragma unroll
            for (int ni = 0; ni < 4; ni++){
                int cl = nwarp + ni*8 + tig*2;
                st[r0*129 + cl]     = acc[mi][ni][0];
                st[r0*129 + cl + 1] = acc[mi][ni][1];
                st[r1*129 + cl]     = acc[mi][ni][2];
                st[r1*129 + cl + 1] = acc[mi][ni][3];
            }
        }
        __syncthreads();
        for (int idx = tid; idx < 128*128; idx += 256){
            int orow = idx >> 7;          // = original col
            int ocol = idx & 127;         // = original row
            int grow = cb + orow, gcol = rb + ocol;
            if (grow < Nn && gcol < Nn)
                C[(size_t)grow*Nn + gcol] = st[ocol*129 + orow];
        }
    }
}

// ---------------- launch ----------------
extern "C" void kernel_launch(void* const* d_in, const int* in_sizes, int n_in,
                              void* d_out, int out_size){
    const float*     x   = (const float*)d_in[0];
    const void*      ei  = d_in[1];
    const float*     ea  = (const float*)d_in[2];
    const float*     W1  = (const float*)d_in[3];
    const float*     as1 = (const float*)d_in[4];
    const float*     ad1 = (const float*)d_in[5];
    const float*     We1 = (const float*)d_in[6];
    const float*     ae1 = (const float*)d_in[7];
    const float*     b1  = (const float*)d_in[8];
    const float*     W2  = (const float*)d_in[9];
    const float*     as2 = (const float*)d_in[10];
    const float*     ad2 = (const float*)d_in[11];
    const float*     We2 = (const float*)d_in[12];
    const float*     ae2 = (const float*)d_in[13];
    const float*     b2  = (const float*)d_in[14];
    const float*     Wp  = (const float*)d_in[15];
    const float*     bp  = (const float*)d_in[16];

    int E  = in_sizes[1]/2;
    if (E > EBASE) E = EBASE;
    int ET = E + Nn;

    float* out  = (float*)d_out;
    float* Ahat = out;
    float* P    = out + (size_t)Nn*Nn;
    float* Zo   = P + (size_t)Nn*NKC;

    float *h1, *hl1, *h2p, *zb;
    float *pas1, *pad1, *pas2, *pad2, *den1, *den2, *ex1, *ex2;
    unsigned short *zA, *zB;
    int *degp;
    cudaGetSymbolAddress((void**)&h1,   g_h1);
    cudaGetSymbolAddress((void**)&hl1,  g_hl1);
    cudaGetSymbolAddress((void**)&h2p,  g_h2);
    cudaGetSymbolAddress((void**)&zb,   g_z);
    cudaGetSymbolAddress((void**)&pas1, g_as1);
    cudaGetSymbolAddress((void**)&pad1, g_ad1);
    cudaGetSymbolAddress((void**)&pas2, g_as2);
    cudaGetSymbolAddress((void**)&pad2, g_ad2);
    cudaGetSymbolAddress((void**)&den1, g_den1);
    cudaGetSymbolAddress((void**)&den2, g_den2);
    cudaGetSymbolAddress((void**)&ex1,  g_ex1);
    cudaGetSymbolAddress((void**)&ex2,  g_ex2);
    cudaGetSymbolAddress((void**)&zA,   g_zA);
    cudaGetSymbolAddress((void**)&zB,   g_zB);
    cudaGetSymbolAddress((void**)&degp, g_deg);

    k_detect<<<1, 32>>>((const unsigned*)ei);
    k_convert<<<(2*E + 255)/256, 256>>>(ei, 2*E);
    k_ae<<<1, 32>>>(We1, ae1, We2, ae2);

    // -------- CSR build (once; shared by both layers) --------
    k_zero<<<(Nn + 255)/256, 256>>>((float*)degp, Nn);
    k_hist<<<(ET + 255)/256, 256>>>(E);
    k_scan<<<1, SCT>>>();
    k_fill<<<(ET + 255)/256, 256>>>(E);

    // -------- layer 1 --------
    gemm64<true><<<dim3(HC1/64, (Nn+63)/64), 256>>>(x, W1, h1, Nn, HC1, INC);
    k_attn<<<(Nn*NH*32 + 255)/256, 256>>>(h1, as1, ad1, pas1, pad1, HIDC);

    k_zero<<<(Nn*NH + 255)/256, 256>>>(den1, Nn*NH);
    k_edge_exp<<<(ET + 255)/256, 256>>>(ea, pas1, pad1, ex1, den1, E, 0);
    k_gather<HIDC,1><<<Nn, NH*HIDC>>>(h1, ex1, den1, b1, hl1);

    // -------- layer 2 --------
    gemm64<false><<<dim3(HC2/64, (Nn+63)/64), 256>>>(hl1, W2, h2p, Nn, HC2, HC1);
    k_attn<<<(Nn*NH*32 + 255)/256, 256>>>(h2p, as2, ad2, pas2, pad2, OUTC);

    k_zero<<<(Nn*NH + 255)/256, 256>>>(den2, Nn*NH);
    k_edge_exp<<<(ET + 255)/256, 256>>>(ea, pas2, pad2, ex2, den2, E, NH);
    k_gather<OUTC,0><<<Nn, NH*OUTC>>>(h2p, ex2, den2, b2, hl1);   // output -> hl1

    // -------- head --------
    k_norm<<<(Nn*32 + 255)/256, 256>>>(hl1, zb, Zo);
    k_p<<<(Nn + 255)/256, 256>>>(zb, Wp, bp, P);
    k_pack<<<(MPAD*HC2 + 255)/256, 256>>>(zb, zA, zB);

    const int SYRK_SMEM = 2*BUFB;   // 73728 B (mainloop) >= 128*129*4 (transpose stage)
    cudaFuncSetAttribute(k_syrk_mma, cudaFuncAttributeMaxDynamicSharedMemorySize, SYRK_SMEM);
    k_syrk_mma<<<NTRI, 256, SYRK_SMEM>>>((const char*)zA, (const char*)zB, Ahat);
}

// round 15
// speedup vs baseline: 3.6447x; 1.2591x over previous
#include <cuda_runtime.h>
#include <cuda_fp16.h>
#include <stdint.h>
#include <math.h>

#define Nn   10000
#define INC  128
#define HIDC 128
#define OUTC 64
#define NH   3
#define NKC  10
#define HC1  (NH*HIDC)   /* 384 */
#define HC2  (NH*OUTC)   /* 192 */
#define EBASE 320000
#define ETOTC (EBASE+Nn) /* 330000 */

#define MPAD 10112       /* 79*128 */
#define NTILE 79
#define NTRI  (NTILE*(NTILE+1)/2)   /* 3160 */
#define KCAT 192         /* fp16 single-precision operand */
#define BK   64
#define NIT  (KCAT/BK)   /* 3 */
#define SROW 72          /* smem row stride in fp16 (144B): conflict-free frags */
#define TILEB (128*SROW*2)   /* 18432 B per tile */
#define BUFB  (2*TILEB)      /* 36864 B per buffer (A+B) */

// ---------------- scratch (device globals; no allocation allowed) ----------------
__device__ float    g_h1[Nn*HC1];
__device__ float    g_hl1[Nn*HC1];
__device__ float    g_h2[Nn*HC2];
__device__ float    g_z[Nn*HC2];
__device__ float    g_as1[Nn*NH], g_ad1[Nn*NH], g_as2[Nn*NH], g_ad2[Nn*NH];
__device__ float    g_den1[Nn*NH], g_den2[Nn*NH];
__device__ float    g_ex1[ETOTC*NH], g_ex2[ETOTC*NH];
__device__ float    g_ae[2*NH];
__device__ int      g_ei[2*EBASE];
__device__ int      g_is64;
// CSR by destination
__device__ int      g_deg[Nn];
__device__ int      g_rowptr[Nn+1];
__device__ int      g_epos[Nn];
__device__ int      g_esort[ETOTC];
__device__ int      g_ssort[ETOTC];
__device__ unsigned short g_zH[(size_t)MPAD*KCAT];   // fp16 z (shared A/B operand)

// ---------------- edge-index dtype detect + convert ----------------
__global__ void k_detect(const unsigned* __restrict__ raw){
    if (threadIdx.x == 0){
        int ok64 = 1;
        for (int i = 0; i < 64; i++)
            if (raw[2*i+1] != 0u){ ok64 = 0; break; }
        g_is64 = ok64;
    }
}
__global__ void k_convert(const void* __restrict__ raw, int n){
    int i = blockIdx.x*blockDim.x + threadIdx.x;
    if (i >= n) return;
    if (g_is64) g_ei[i] = (int)((const long long*)raw)[i];
    else        g_ei[i] = ((const int*)raw)[i];
}

// ---------------- CSR build ----------------
__global__ void k_hist(int E){
    int e = blockIdx.x*blockDim.x + threadIdx.x;
    if (e >= E + Nn) return;
    int d = (e < E) ? g_ei[E+e] : (e - E);
    atomicAdd(&g_deg[d], 1);
}
#define SCT 1024
#define SCHUNK ((Nn + SCT - 1)/SCT)
__global__ void __launch_bounds__(SCT) k_scan(){
    __shared__ int part[SCT];
    int t = threadIdx.x;
    int base = t*SCHUNK;
    int s = 0;
    for (int j = 0; j < SCHUNK; j++){
        int idx = base + j;
        if (idx < Nn) s += g_deg[idx];
    }
    part[t] = s;
    __syncthreads();
    for (int off = 1; off < SCT; off <<= 1){
        int v = (t >= off) ? part[t-off] : 0;
        __syncthreads();
        part[t] += v;
        __syncthreads();
    }
    int run = (t == 0) ? 0 : part[t-1];
    for (int j = 0; j < SCHUNK; j++){
        int idx = base + j;
        if (idx < Nn){
            g_rowptr[idx] = run;
            g_epos[idx]   = run;
            run += g_deg[idx];
        }
    }
    if (t == SCT-1) g_rowptr[Nn] = run;
}
__global__ void k_fill(int E){
    int e = blockIdx.x*blockDim.x + threadIdx.x;
    if (e >= E + Nn) return;
    int s, d;
    if (e < E){ s = g_ei[e]; d = g_ei[E+e]; }
    else      { s = e - E; d = s; }
    int pos = atomicAdd(&g_epos[d], 1);
    g_esort[pos] = e;
    g_ssort[pos] = s;
}

// ---------------- misc ----------------
__global__ void k_zero(float* p, int n){
    int i = blockIdx.x*blockDim.x + threadIdx.x;
    if (i < n) p[i] = 0.f;
}

__global__ void k_ae(const float* We1, const float* ate1, const float* We2, const float* ate2){
    int t = threadIdx.x;
    if (t < NH){
        float s = 0.f;
        for (int c = 0; c < HIDC; c++) s += We1[t*HIDC+c]*ate1[t*HIDC+c];
        g_ae[t] = s;
    } else if (t < 2*NH){
        int h = t - NH; float s = 0.f;
        for (int c = 0; c < OUTC; c++) s += We2[h*OUTC+c]*ate2[h*OUTC+c];
        g_ae[NH+h] = s;
    }
}

// ---------------- generic 64x64x16 fp32 GEMM (row-major NN) ----------------
template<bool SAN>
__global__ void __launch_bounds__(256) gemm64(const float* __restrict__ A,
                                              const float* __restrict__ B,
                                              float* __restrict__ C,
                                              int M, int Ncol, int K){
    __shared__ float As[16][64];
    __shared__ float Bs[16][64];
    int rb = blockIdx.y*64, cb = blockIdx.x*64;
    int tid = threadIdx.x;
    int tx = tid & 15, ty = tid >> 4;
    float acc[4][4] = {};
    for (int k0 = 0; k0 < K; k0 += 16){
        {
            int r = tid >> 2, k4 = (tid & 3)*4;
            float4 v = make_float4(0.f,0.f,0.f,0.f);
            if (rb + r < M) v = *(const float4*)(A + (size_t)(rb+r)*K + k0 + k4);
            if (SAN){
                v.x = isnan(v.x)?0.f:v.x; v.y = isnan(v.y)?0.f:v.y;
                v.z = isnan(v.z)?0.f:v.z; v.w = isnan(v.w)?0.f:v.w;
            }
            As[k4+0][r]=v.x; As[k4+1][r]=v.y; As[k4+2][r]=v.z; As[k4+3][r]=v.w;
        }
        {
            int kr = tid >> 4, c4 = (tid & 15)*4;
            *(float4*)&Bs[kr][c4] = *(const float4*)(B + (size_t)(k0+kr)*Ncol + cb + c4);
        }
        __syncthreads();
        #pragma unroll
        for (int k = 0; k < 16; k++){
            float4 a4 = *(float4*)&As[k][ty*4];
            float4 b4 = *(float4*)&Bs[k][tx*4];
            float av[4] = {a4.x,a4.y,a4.z,a4.w};
            float bv[4] = {b4.x,b4.y,b4.z,b4.w};
            #pragma unroll
            for (int i = 0; i < 4; i++)
                #pragma unroll
                for (int j = 0; j < 4; j++)
                    acc[i][j] += av[i]*bv[j];
        }
        __syncthreads();
    }
    #pragma unroll
    for (int i = 0; i < 4; i++){
        int row = rb + ty*4 + i;
        if (row < M)
            *(float4*)(C + (size_t)row*Ncol + cb + tx*4) =
                make_float4(acc[i][0],acc[i][1],acc[i][2],acc[i][3]);
    }
}

// ---------------- attention logits ----------------
__global__ void k_attn(const float* __restrict__ hfeat, const float* __restrict__ atts,
                       const float* __restrict__ attd, float* __restrict__ as_,
                       float* __restrict__ ad_, int C){
    int gw   = (blockIdx.x*blockDim.x + threadIdx.x) >> 5;
    int lane = threadIdx.x & 31;
    if (gw >= Nn*NH) return;
    int n = gw / NH, hh = gw % NH;
    const float* hp = hfeat + (size_t)n*NH*C + hh*C;
    float s = 0.f, d = 0.f;
    for (int c = lane; c < C; c += 32){
        float v = hp[c];
        s += v*atts[hh*C+c];
        d += v*attd[hh*C+c];
    }
    #pragma unroll
    for (int o = 16; o; o >>= 1){
        s += __shfl_xor_sync(0xffffffffu, s, o);
        d += __shfl_xor_sync(0xffffffffu, d, o);
    }
    if (lane == 0){ as_[gw] = s; ad_[gw] = d; }
}

// ---------------- edge exp (no max shift: coefs are shift-invariant) ----------------
__global__ void k_edge_exp(const float* __restrict__ ea,
                           const float* __restrict__ as_, const float* __restrict__ ad_,
                           float* __restrict__ exbuf, float* __restrict__ den,
                           int E, int aeoff){
    int e = blockIdx.x*blockDim.x + threadIdx.x;
    if (e >= E + Nn) return;
    int s, d; float w;
    if (e < E){ s = g_ei[e]; d = g_ei[E+e]; w = ea[e]; }
    else      { s = e - E; d = s; w = 1.f; }
    #pragma unroll
    for (int h = 0; h < NH; h++){
        float a = as_[s*NH+h] + ad_[d*NH+h] + w*g_ae[aeoff+h];
        a = a > 0.f ? a : 0.2f*a;
        float x = __expf(a);
        exbuf[(size_t)e*NH+h] = x;
        atomicAdd(&den[d*NH+h], x);
    }
}

// ---------------- CSR gather with fused normalization + bias (+ELU) ----------------
template<int C, int ELU>
__global__ void k_gather(const float* __restrict__ hfeat,
                         const float* __restrict__ exbuf,
                         const float* __restrict__ den,
                         const float* __restrict__ b,
                         float* __restrict__ o){
    int n = blockIdx.x;
    int t = threadIdx.x;              // blockDim = NH*C
    int h = t / C;
    float invd = 1.f / (den[n*NH + h] + 1e-16f);
    int beg = g_rowptr[n], end = g_rowptr[n+1];
    float acc = 0.f;
    for (int p = beg; p < end; p++){
        int e = g_esort[p];
        int s = g_ssort[p];
        acc += hfeat[(size_t)s*(NH*C) + t] * exbuf[(size_t)e*NH + h];
    }
    float v = acc*invd + b[t];
    if (ELU) v = v > 0.f ? v : expm1f(v);
    o[(size_t)n*(NH*C) + t] = v;
}

// ---------------- L2 normalize ----------------
__global__ void k_norm(const float* __restrict__ h, float* __restrict__ z,
                       float* __restrict__ zo){
    int gw   = (blockIdx.x*blockDim.x + threadIdx.x) >> 5;
    int lane = threadIdx.x & 31;
    if (gw >= Nn) return;
    const float* r = h + (size_t)gw*HC2;
    float s = 0.f;
    for (int c = lane; c < HC2; c += 32){ float v = r[c]; s += v*v; }
    #pragma unroll
    for (int o = 16; o; o >>= 1) s += __shfl_xor_sync(0xffffffffu, s, o);
    float inv = 1.f / fmaxf(sqrtf(s), 1e-12f);
    for (int c = lane; c < HC2; c += 32){
        float v = r[c]*inv;
        z[(size_t)gw*HC2+c]  = v;
        zo[(size_t)gw*HC2+c] = v;
    }
}

// ---------------- p = softmax(z @ Wp + bp) ----------------
__global__ void k_p(const float* __restrict__ z, const float* __restrict__ Wp,
                    const float* __restrict__ bp, float* __restrict__ P){
    __shared__ float sW[HC2*NKC];
    __shared__ float sb[NKC];
    for (int i = threadIdx.x; i < HC2*NKC; i += blockDim.x) sW[i] = Wp[i];
    if (threadIdx.x < NKC) sb[threadIdx.x] = bp[threadIdx.x];
    __syncthreads();
    int n = blockIdx.x*blockDim.x + threadIdx.x;
    if (n >= Nn) return;
    float lg[NKC];
    #pragma unroll
    for (int k = 0; k < NKC; k++) lg[k] = sb[k];
    const float* zr = z + (size_t)n*HC2;
    for (int c = 0; c < HC2; c++){
        float v = zr[c];
        #pragma unroll
        for (int k = 0; k < NKC; k++) lg[k] += v*sW[c*NKC+k];
    }
    float mx = lg[0];
    #pragma unroll
    for (int k = 1; k < NKC; k++) mx = fmaxf(mx, lg[k]);
    float sum = 0.f;
    #pragma unroll
    for (int k = 0; k < NKC; k++){ lg[k] = __expf(lg[k]-mx); sum += lg[k]; }
    float inv = 1.f/sum;
    #pragma unroll
    for (int k = 0; k < NKC; k++) P[(size_t)n*NKC+k] = lg[k]*inv;
}

// ---------------- pack z into fp16 operand (shared by A and B sides) ----------------
__global__ void k_pack(const float* __restrict__ z, unsigned short* __restrict__ ZH){
    int i = blockIdx.x*blockDim.x + threadIdx.x;
    if (i >= MPAD*HC2) return;
    int n = i / HC2, c = i - n*HC2;
    float v = (n < Nn) ? z[(size_t)n*HC2 + c] : 0.f;
    __half hv = __float2half(v);
    ZH[(size_t)n*KCAT + c] = __half_as_ushort(hv);
}

// ---------------- helpers ----------------
__device__ __forceinline__ uint32_t smem_u32(const void* p){
    uint32_t a;
    asm("{ .reg .u64 t; cvta.to.shared.u64 t, %1; cvt.u32.u64 %0, t; }" : "=r"(a) : "l"(p));
    return a;
}
__device__ __forceinline__ void cpasync16(uint32_t dst, const void* src){
    asm volatile("cp.async.cg.shared.global [%0], [%1], 16;" :: "r"(dst), "l"(src));
}
__device__ __forceinline__ void cp_commit(){
    asm volatile("cp.async.commit_group;");
}
template<int N>
__device__ __forceinline__ void cp_wait(){
    asm volatile("cp.async.wait_group %0;" :: "n"(N));
}
__device__ __forceinline__ void mma16816(float* c, const uint32_t* a, const uint32_t* b){
    asm volatile(
        "mma.sync.aligned.m16n8k16.row.col.f32.f16.f16.f32 "
        "{%0,%1,%2,%3}, {%4,%5,%6,%7}, {%8,%9}, {%0,%1,%2,%3};"
        : "+f"(c[0]), "+f"(c[1]), "+f"(c[2]), "+f"(c[3])
        : "r"(a[0]), "r"(a[1]), "r"(a[2]), "r"(a[3]), "r"(b[0]), "r"(b[1]));
}

// async-load one 128xBK tile pair (A rows rb.., B rows cb..) for k-chunk kc
__device__ __forceinline__ void tile_load(const char* __restrict__ GZ,
                                          uint32_t sA, uint32_t sB,
                                          int rb, int cb, int kc, int tid){
    #pragma unroll
    for (int i = 0; i < 4; i++){
        int chunk = tid + i*256;          // 1024 chunks of 16B per tile
        int row = chunk >> 3, seg = chunk & 7;
        size_t gofs = ((size_t)KCAT*row + kc*BK + seg*8) * 2;
        cpasync16(sA + row*(SROW*2) + seg*16, GZ + (size_t)(rb)*KCAT*2 + gofs);
        cpasync16(sB + row*(SROW*2) + seg*16, GZ + (size_t)(cb)*KCAT*2 + gofs);
    }
}

// ---------------- A_hat = zH zH^T, upper-triangular tiles + mirror ----------------
__global__ void __launch_bounds__(256) k_syrk_mma(const char* __restrict__ ZH,
                                                  float* __restrict__ C){
    extern __shared__ char dsm[];
    uint32_t s0 = smem_u32(dsm);

    int tid  = threadIdx.x;
    int wid  = tid >> 5, lane = tid & 31;
    int gid  = lane >> 2, tig = lane & 3;
    int mwarp = (wid & 1) * 64;       // 2 warp-rows
    int nwarp = (wid >> 1) * 32;      // 4 warp-cols

    // decode upper-triangular tile (i <= j) from linear block id
    int ti = 0, rem = blockIdx.x;
    while (rem >= NTILE - ti){ rem -= NTILE - ti; ti++; }
    int tj = ti + rem;
    int rb = ti * 128, cb = tj * 128;

    float acc[4][4][4];
    #pragma unroll
    for (int a = 0; a < 4; a++)
        #pragma unroll
        for (int b = 0; b < 4; b++)
            #pragma unroll
            for (int c = 0; c < 4; c++) acc[a][b][c] = 0.f;

    tile_load(ZH, s0, s0 + TILEB, rb, cb, 0, tid);
    cp_commit();

    for (int it = 0; it < NIT; it++){
        int s = it & 1;
        if (it + 1 < NIT){
            int ns = (it + 1) & 1;
            tile_load(ZH, s0 + ns*BUFB, s0 + ns*BUFB + TILEB, rb, cb, it + 1, tid);
            cp_commit();
            cp_wait<1>();
        } else {
            cp_wait<0>();
        }
        __syncthreads();

        const uint32_t* As32 = (const uint32_t*)(dsm + s*BUFB);
        const uint32_t* Bs32 = (const uint32_t*)(dsm + s*BUFB + TILEB);

        #pragma unroll
        for (int kk = 0; kk < BK/16; kk++){
            uint32_t af[4][4];
            #pragma unroll
            for (int mi = 0; mi < 4; mi++){
                const uint32_t* base = As32 + (size_t)(mwarp + mi*16 + gid)*(SROW/2) + tig + kk*8;
                af[mi][0] = base[0];
                af[mi][1] = base[8*(SROW/2)];
                af[mi][2] = base[4];
                af[mi][3] = base[8*(SROW/2) + 4];
            }
            uint32_t bf[4][2];
            #pragma unroll
            for (int ni = 0; ni < 4; ni++){
                const uint32_t* bb = Bs32 + (size_t)(nwarp + ni*8 + gid)*(SROW/2) + tig + kk*8;
                bf[ni][0] = bb[0];
                bf[ni][1] = bb[4];
            }
            #pragma unroll
            for (int mi = 0; mi < 4; mi++)
                #pragma unroll
                for (int ni = 0; ni < 4; ni++)
                    mma16816(acc[mi][ni], af[mi], bf[ni]);
        }
        __syncthreads();
    }

    // direct write (rows rb.., cols cb..)
    #pragma unroll
    for (int mi = 0; mi < 4; mi++){
        int r0 = rb + mwarp + mi*16 + gid;
        int r1 = r0 + 8;
        #pragma unroll
        for (int ni = 0; ni < 4; ni++){
            int col = cb + nwarp + ni*8 + tig*2;
            if (col + 1 < Nn){
                if (r0 < Nn)
                    *(float2*)(C + (size_t)r0*Nn + col) = make_float2(acc[mi][ni][0], acc[mi][ni][1]);
                if (r1 < Nn)
                    *(float2*)(C + (size_t)r1*Nn + col) = make_float2(acc[mi][ni][2], acc[mi][ni][3]);
            }
        }
    }

    // mirror write for off-diagonal tiles: C[cb+c, rb+r] = tile[r][c]
    if (ti != tj){
        float* st = (float*)dsm;          // 128 x 128, stride 129 (conflict-free transpose read)
        __syncthreads();                  // mainloop smem no longer needed
        #pragma unroll
        for (int mi = 0; mi < 4; mi++){
            int r0 = mwarp + mi*16 + gid;
            int r1 = r0 + 8;
            #pragma unroll
            for (int ni = 0; ni < 4; ni++){
                int cl = nwarp + ni*8 + tig*2;
                st[r0*129 + cl]     = acc[mi][ni][0];
                st[r0*129 + cl + 1] = acc[mi][ni][1];
                st[r1*129 + cl]     = acc[mi][ni][2];
                st[r1*129 + cl + 1] = acc[mi][ni][3];
            }
        }
        __syncthreads();
        for (int idx = tid; idx < 128*128; idx += 256){
            int orow = idx >> 7;          // = original col
            int ocol = idx & 127;         // = original row
            int grow = cb + orow, gcol = rb + ocol;
            if (grow < Nn && gcol < Nn)
                C[(size_t)grow*Nn + gcol] = st[ocol*129 + orow];
        }
    }
}

// ---------------- launch ----------------
extern "C" void kernel_launch(void* const* d_in, const int* in_sizes, int n_in,
                              void* d_out, int out_size){
    const float*     x   = (const float*)d_in[0];
    const void*      ei  = d_in[1];
    const float*     ea  = (const float*)d_in[2];
    const float*     W1  = (const float*)d_in[3];
    const float*     as1 = (const float*)d_in[4];
    const float*     ad1 = (const float*)d_in[5];
    const float*     We1 = (const float*)d_in[6];
    const float*     ae1 = (const float*)d_in[7];
    const float*     b1  = (const float*)d_in[8];
    const float*     W2  = (const float*)d_in[9];
    const float*     as2 = (const float*)d_in[10];
    const float*     ad2 = (const float*)d_in[11];
    const float*     We2 = (const float*)d_in[12];
    const float*     ae2 = (const float*)d_in[13];
    const float*     b2  = (const float*)d_in[14];
    const float*     Wp  = (const float*)d_in[15];
    const float*     bp  = (const float*)d_in[16];

    int E  = in_sizes[1]/2;
    if (E > EBASE) E = EBASE;
    int ET = E + Nn;

    float* out  = (float*)d_out;
    float* Ahat = out;
    float* P    = out + (size_t)Nn*Nn;
    float* Zo   = P + (size_t)Nn*NKC;

    float *h1, *hl1, *h2p, *zb;
    float *pas1, *pad1, *pas2, *pad2, *den1, *den2, *ex1, *ex2;
    unsigned short *zH;
    int *degp;
    cudaGetSymbolAddress((void**)&h1,   g_h1);
    cudaGetSymbolAddress((void**)&hl1,  g_hl1);
    cudaGetSymbolAddress((void**)&h2p,  g_h2);
    cudaGetSymbolAddress((void**)&zb,   g_z);
    cudaGetSymbolAddress((void**)&pas1, g_as1);
    cudaGetSymbolAddress((void**)&pad1, g_ad1);
    cudaGetSymbolAddress((void**)&pas2, g_as2);
    cudaGetSymbolAddress((void**)&pad2, g_ad2);
    cudaGetSymbolAddress((void**)&den1, g_den1);
    cudaGetSymbolAddress((void**)&den2, g_den2);
    cudaGetSymbolAddress((void**)&ex1,  g_ex1);
    cudaGetSymbolAddress((void**)&ex2,  g_ex2);
    cudaGetSymbolAddress((void**)&zH,   g_zH);
    cudaGetSymbolAddress((void**)&degp, g_deg);

    k_detect<<<1, 32>>>((const unsigned*)ei);
    k_convert<<<(2*E + 255)/256, 256>>>(ei, 2*E);
    k_ae<<<1, 32>>>(We1, ae1, We2, ae2);

    // -------- CSR build (once; shared by both layers) --------
    k_zero<<<(Nn + 255)/256, 256>>>((float*)degp, Nn);
    k_hist<<<(ET + 255)/256, 256>>>(E);
    k_scan<<<1, SCT>>>();
    k_fill<<<(ET + 255)/256, 256>>>(E);

    // -------- layer 1 --------
    gemm64<true><<<dim3(HC1/64, (Nn+63)/64), 256>>>(x, W1, h1, Nn, HC1, INC);
    k_attn<<<(Nn*NH*32 + 255)/256, 256>>>(h1, as1, ad1, pas1, pad1, HIDC);

    k_zero<<<(Nn*NH + 255)/256, 256>>>(den1, Nn*NH);
    k_edge_exp<<<(ET + 255)/256, 256>>>(ea, pas1, pad1, ex1, den1, E, 0);
    k_gather<HIDC,1><<<Nn, NH*HIDC>>>(h1, ex1, den1, b1, hl1);

    // -------- layer 2 --------
    gemm64<false><<<dim3(HC2/64, (Nn+63)/64), 256>>>(hl1, W2, h2p, Nn, HC2, HC1);
    k_attn<<<(Nn*NH*32 + 255)/256, 256>>>(h2p, as2, ad2, pas2, pad2, OUTC);

    k_zero<<<(Nn*NH + 255)/256, 256>>>(den2, Nn*NH);
    k_edge_exp<<<(ET + 255)/256, 256>>>(ea, pas2, pad2, ex2, den2, E, NH);
    k_gather<OUTC,0><<<Nn, NH*OUTC>>>(h2p, ex2, den2, b2, hl1);   // output -> hl1

    // -------- head --------
    k_norm<<<(Nn*32 + 255)/256, 256>>>(hl1, zb, Zo);
    k_p<<<(Nn + 255)/256, 256>>>(zb, Wp, bp, P);
    k_pack<<<(MPAD*HC2 + 255)/256, 256>>>(zb, zH);

    const int SYRK_SMEM = 2*BUFB;   // 73728 B (mainloop) >= 128*129*4 (transpose stage)
    cudaFuncSetAttribute(k_syrk_mma, cudaFuncAttributeMaxDynamicSharedMemorySize, SYRK_SMEM);
    k_syrk_mma<<<NTRI, 256, SYRK_SMEM>>>((const char*)zH, Ahat);
}

// round 17
// speedup vs baseline: 3.8969x; 1.0692x over previous
#include <cuda_runtime.h>
#include <cuda_fp16.h>
#include <stdint.h>
#include <math.h>

#define Nn   10000
#define INC  128
#define HIDC 128
#define OUTC 64
#define NH   3
#define NKC  10
#define HC1  (NH*HIDC)   /* 384 */
#define HC2  (NH*OUTC)   /* 192 */
#define EBASE 320000
#define ETOTC (EBASE+Nn) /* 330000 */

#define MPAD 10112       /* 79*128 */
#define NTILE 79
#define NTRI  (NTILE*(NTILE+1)/2)   /* 3160 */
#define KCAT 192         /* fp16 single-precision operand */
#define BK   64
#define NIT  (KCAT/BK)   /* 3 */
#define SROW 72          /* smem row stride in fp16 (144B): conflict-free frags */
#define TILEB (128*SROW*2)   /* 18432 B per tile */
#define BUFB  (2*TILEB)      /* 36864 B per buffer (A+B) */

// ---------------- scratch (device globals; no allocation allowed) ----------------
__device__ float    g_h1[Nn*HC1];
__device__ float    g_hl1[Nn*HC1];
__device__ float    g_h2[Nn*HC2];
__device__ float    g_z[Nn*HC2];
__device__ float    g_as1[Nn*NH], g_ad1[Nn*NH], g_as2[Nn*NH], g_ad2[Nn*NH];
__device__ float    g_ae[2*NH];
__device__ int      g_ei[2*EBASE];
__device__ int      g_is64;
// CSR by destination
__device__ int      g_deg[Nn];
__device__ int      g_rowptr[Nn+1];
__device__ int      g_epos[Nn];
__device__ int      g_esort[ETOTC];
__device__ int      g_ssort[ETOTC];
__device__ unsigned short g_zH[(size_t)MPAD*KCAT];   // fp16 z (shared A/B operand)

// ---------------- edge-index dtype detect + convert ----------------
__global__ void k_detect(const unsigned* __restrict__ raw){
    if (threadIdx.x == 0){
        int ok64 = 1;
        for (int i = 0; i < 64; i++)
            if (raw[2*i+1] != 0u){ ok64 = 0; break; }
        g_is64 = ok64;
    }
}
__global__ void k_convert(const void* __restrict__ raw, int n){
    int i = blockIdx.x*blockDim.x + threadIdx.x;
    if (i >= n) return;
    if (g_is64) g_ei[i] = (int)((const long long*)raw)[i];
    else        g_ei[i] = ((const int*)raw)[i];
}

// ---------------- CSR build ----------------
__global__ void k_hist(int E){
    int e = blockIdx.x*blockDim.x + threadIdx.x;
    if (e >= E + Nn) return;
    int d = (e < E) ? g_ei[E+e] : (e - E);
    atomicAdd(&g_deg[d], 1);
}
#define SCT 1024
#define SCHUNK ((Nn + SCT - 1)/SCT)
__global__ void __launch_bounds__(SCT) k_scan(){
    __shared__ int part[SCT];
    int t = threadIdx.x;
    int base = t*SCHUNK;
    int s = 0;
    for (int j = 0; j < SCHUNK; j++){
        int idx = base + j;
        if (idx < Nn) s += g_deg[idx];
    }
    part[t] = s;
    __syncthreads();
    for (int off = 1; off < SCT; off <<= 1){
        int v = (t >= off) ? part[t-off] : 0;
        __syncthreads();
        part[t] += v;
        __syncthreads();
    }
    int run = (t == 0) ? 0 : part[t-1];
    for (int j = 0; j < SCHUNK; j++){
        int idx = base + j;
        if (idx < Nn){
            g_rowptr[idx] = run;
            g_epos[idx]   = run;
            run += g_deg[idx];
        }
    }
    if (t == SCT-1) g_rowptr[Nn] = run;
}
__global__ void k_fill(int E){
    int e = blockIdx.x*blockDim.x + threadIdx.x;
    if (e >= E + Nn) return;
    int s, d;
    if (e < E){ s = g_ei[e]; d = g_ei[E+e]; }
    else      { s = e - E; d = s; }
    int pos = atomicAdd(&g_epos[d], 1);
    g_esort[pos] = e;
    g_ssort[pos] = s;
}

// ---------------- misc ----------------
__global__ void k_zero(float* p, int n){
    int i = blockIdx.x*blockDim.x + threadIdx.x;
    if (i < n) p[i] = 0.f;
}

__global__ void k_ae(const float* We1, const float* ate1, const float* We2, const float* ate2){
    int t = threadIdx.x;
    if (t < NH){
        float s = 0.f;
        for (int c = 0; c < HIDC; c++) s += We1[t*HIDC+c]*ate1[t*HIDC+c];
        g_ae[t] = s;
    } else if (t < 2*NH){
        int h = t - NH; float s = 0.f;
        for (int c = 0; c < OUTC; c++) s += We2[h*OUTC+c]*ate2[h*OUTC+c];
        g_ae[NH+h] = s;
    }
}

// ---------------- generic 64x64x16 fp32 GEMM (row-major NN) ----------------
template<bool SAN>
__global__ void __launch_bounds__(256) gemm64(const float* __restrict__ A,
                                              const float* __restrict__ B,
                                              float* __restrict__ C,
                                              int M, int Ncol, int K){
    __shared__ float As[16][64];
    __shared__ float Bs[16][64];
    int rb = blockIdx.y*64, cb = blockIdx.x*64;
    int tid = threadIdx.x;
    int tx = tid & 15, ty = tid >> 4;
    float acc[4][4] = {};
    for (int k0 = 0; k0 < K; k0 += 16){
        {
            int r = tid >> 2, k4 = (tid & 3)*4;
            float4 v = make_float4(0.f,0.f,0.f,0.f);
            if (rb + r < M) v = *(const float4*)(A + (size_t)(rb+r)*K + k0 + k4);
            if (SAN){
                v.x = isnan(v.x)?0.f:v.x; v.y = isnan(v.y)?0.f:v.y;
                v.z = isnan(v.z)?0.f:v.z; v.w = isnan(v.w)?0.f:v.w;
            }
            As[k4+0][r]=v.x; As[k4+1][r]=v.y; As[k4+2][r]=v.z; As[k4+3][r]=v.w;
        }
        {
            int kr = tid >> 4, c4 = (tid & 15)*4;
            *(float4*)&Bs[kr][c4] = *(const float4*)(B + (size_t)(k0+kr)*Ncol + cb + c4);
        }
        __syncthreads();
        #pragma unroll
        for (int k = 0; k < 16; k++){
            float4 a4 = *(float4*)&As[k][ty*4];
            float4 b4 = *(float4*)&Bs[k][tx*4];
            float av[4] = {a4.x,a4.y,a4.z,a4.w};
            float bv[4] = {b4.x,b4.y,b4.z,b4.w};
            #pragma unroll
            for (int i = 0; i < 4; i++)
                #pragma unroll
                for (int j = 0; j < 4; j++)
                    acc[i][j] += av[i]*bv[j];
        }
        __syncthreads();
    }
    #pragma unroll
    for (int i = 0; i < 4; i++){
        int row = rb + ty*4 + i;
        if (row < M)
            *(float4*)(C + (size_t)row*Ncol + cb + tx*4) =
                make_float4(acc[i][0],acc[i][1],acc[i][2],acc[i][3]);
    }
}

// ---------------- attention logits ----------------
__global__ void k_attn(const float* __restrict__ hfeat, const float* __restrict__ atts,
                       const float* __restrict__ attd, float* __restrict__ as_,
                       float* __restrict__ ad_, int C){
    int gw   = (blockIdx.x*blockDim.x + threadIdx.x) >> 5;
    int lane = threadIdx.x & 31;
    if (gw >= Nn*NH) return;
    int n = gw / NH, hh = gw % NH;
    const float* hp = hfeat + (size_t)n*NH*C + hh*C;
    float s = 0.f, d = 0.f;
    for (int c = lane; c < C; c += 32){
        float v = hp[c];
        s += v*atts[hh*C+c];
        d += v*attd[hh*C+c];
    }
    #pragma unroll
    for (int o = 16; o; o >>= 1){
        s += __shfl_xor_sync(0xffffffffu, s, o);
        d += __shfl_xor_sync(0xffffffffu, d, o);
    }
    if (lane == 0){ as_[gw] = s; ad_[gw] = d; }
}

// ---------------- fused edge-softmax + CSR gather + bias (+ELU) ----------------
// Per block n: compute exp(leaky(logit)) for the segment in 128-edge chunks in
// smem, accumulate per-head denominator, gather-normalize in one pass.
#define GCH 128
template<int C, int ELU>
__global__ void k_gather2(const float* __restrict__ hfeat,
                          const float* __restrict__ ea,
                          const float* __restrict__ as_,
                          const float* __restrict__ ad_,
                          const float* __restrict__ b,
                          float* __restrict__ o, int E, int aeoff){
    __shared__ float exs[GCH*NH];
    __shared__ int   ssm[GCH];
    __shared__ float dsum[NH];
    int n = blockIdx.x;
    int t = threadIdx.x;              // blockDim = NH*C (384 or 192)
    int h = t / C;
    int beg = g_rowptr[n], end = g_rowptr[n+1];
    if (t < NH) dsum[t] = 0.f;
    float acc = 0.f;
    for (int cb = beg; cb < end; cb += GCH){
        int clen = min(GCH, end - cb);
        __syncthreads();                       // protect smem from previous chunk readers
        if (t < clen){
            int p = cb + t;
            int e = g_esort[p], s = g_ssort[p];
            ssm[t] = s;
            float w = (e < E) ? ea[e] : 1.f;
            #pragma unroll
            for (int hh = 0; hh < NH; hh++){
                float a = as_[s*NH+hh] + ad_[n*NH+hh] + w*g_ae[aeoff+hh];
                a = a > 0.f ? a : 0.2f*a;
                exs[t*NH+hh] = __expf(a);
            }
        }
        __syncthreads();
        if (t < NH){
            float sd = 0.f;
            for (int j = 0; j < clen; j++) sd += exs[j*NH+t];
            dsum[t] += sd;
        }
        for (int j = 0; j < clen; j++)
            acc += hfeat[(size_t)ssm[j]*(NH*C) + t] * exs[j*NH+h];
    }
    __syncthreads();
    float v = acc / (dsum[h] + 1e-16f) + b[t];
    if (ELU) v = v > 0.f ? v : expm1f(v);
    o[(size_t)n*(NH*C) + t] = v;
}

// ---------------- L2 normalize ----------------
__global__ void k_norm(const float* __restrict__ h, float* __restrict__ z,
                       float* __restrict__ zo){
    int gw   = (blockIdx.x*blockDim.x + threadIdx.x) >> 5;
    int lane = threadIdx.x & 31;
    if (gw >= Nn) return;
    const float* r = h + (size_t)gw*HC2;
    float s = 0.f;
    for (int c = lane; c < HC2; c += 32){ float v = r[c]; s += v*v; }
    #pragma unroll
    for (int o = 16; o; o >>= 1) s += __shfl_xor_sync(0xffffffffu, s, o);
    float inv = 1.f / fmaxf(sqrtf(s), 1e-12f);
    for (int c = lane; c < HC2; c += 32){
        float v = r[c]*inv;
        z[(size_t)gw*HC2+c]  = v;
        zo[(size_t)gw*HC2+c] = v;
    }
}

// ---------------- p = softmax(z @ Wp + bp) ----------------
__global__ void k_p(const float* __restrict__ z, const float* __restrict__ Wp,
                    const float* __restrict__ bp, float* __restrict__ P){
    __shared__ float sW[HC2*NKC];
    __shared__ float sb[NKC];
    for (int i = threadIdx.x; i < HC2*NKC; i += blockDim.x) sW[i] = Wp[i];
    if (threadIdx.x < NKC) sb[threadIdx.x] = bp[threadIdx.x];
    __syncthreads();
    int n = blockIdx.x*blockDim.x + threadIdx.x;
    if (n >= Nn) return;
    float lg[NKC];
    #pragma unroll
    for (int k = 0; k < NKC; k++) lg[k] = sb[k];
    const float* zr = z + (size_t)n*HC2;
    for (int c = 0; c < HC2; c++){
        float v = zr[c];
        #pragma unroll
        for (int k = 0; k < NKC; k++) lg[k] += v*sW[c*NKC+k];
    }
    float mx = lg[0];
    #pragma unroll
    for (int k = 1; k < NKC; k++) mx = fmaxf(mx, lg[k]);
    float sum = 0.f;
    #pragma unroll
    for (int k = 0; k < NKC; k++){ lg[k] = __expf(lg[k]-mx); sum += lg[k]; }
    float inv = 1.f/sum;
    #pragma unroll
    for (int k = 0; k < NKC; k++) P[(size_t)n*NKC+k] = lg[k]*inv;
}

// ---------------- pack z into fp16 operand (shared by A and B sides) ----------------
__global__ void k_pack(const float* __restrict__ z, unsigned short* __restrict__ ZH){
    int i = blockIdx.x*blockDim.x + threadIdx.x;
    if (i >= MPAD*HC2) return;
    int n = i / HC2, c = i - n*HC2;
    float v = (n < Nn) ? z[(size_t)n*HC2 + c] : 0.f;
    __half hv = __float2half(v);
    ZH[(size_t)n*KCAT + c] = __half_as_ushort(hv);
}

// ---------------- helpers ----------------
__device__ __forceinline__ uint32_t smem_u32(const void* p){
    uint32_t a;
    asm("{ .reg .u64 t; cvta.to.shared.u64 t, %1; cvt.u32.u64 %0, t; }" : "=r"(a) : "l"(p));
    return a;
}
__device__ __forceinline__ void cpasync16(uint32_t dst, const void* src){
    asm volatile("cp.async.cg.shared.global [%0], [%1], 16;" :: "r"(dst), "l"(src));
}
__device__ __forceinline__ void cp_commit(){
    asm volatile("cp.async.commit_group;");
}
template<int N>
__device__ __forceinline__ void cp_wait(){
    asm volatile("cp.async.wait_group %0;" :: "n"(N));
}
__device__ __forceinline__ void mma16816(float* c, const uint32_t* a, const uint32_t* b){
    asm volatile(
        "mma.sync.aligned.m16n8k16.row.col.f32.f16.f16.f32 "
        "{%0,%1,%2,%3}, {%4,%5,%6,%7}, {%8,%9}, {%0,%1,%2,%3};"
        : "+f"(c[0]), "+f"(c[1]), "+f"(c[2]), "+f"(c[3])
        : "r"(a[0]), "r"(a[1]), "r"(a[2]), "r"(a[3]), "r"(b[0]), "r"(b[1]));
}

// async-load one 128xBK tile pair (A rows rb.., B rows cb..) for k-chunk kc
__device__ __forceinline__ void tile_load(const char* __restrict__ GZ,
                                          uint32_t sA, uint32_t sB,
                                          int rb, int cb, int kc, int tid){
    #pragma unroll
    for (int i = 0; i < 4; i++){
        int chunk = tid + i*256;          // 1024 chunks of 16B per tile
        int row = chunk >> 3, seg = chunk & 7;
        size_t gofs = ((size_t)KCAT*row + kc*BK + seg*8) * 2;
        cpasync16(sA + row*(SROW*2) + seg*16, GZ + (size_t)(rb)*KCAT*2 + gofs);
        cpasync16(sB + row*(SROW*2) + seg*16, GZ + (size_t)(cb)*KCAT*2 + gofs);
    }
}

// ---------------- A_hat = zH zH^T, upper-triangular tiles + mirror ----------------
__global__ void __launch_bounds__(256) k_syrk_mma(const char* __restrict__ ZH,
                                                  float* __restrict__ C){
    extern __shared__ char dsm[];
    uint32_t s0 = smem_u32(dsm);

    int tid  = threadIdx.x;
    int wid  = tid >> 5, lane = tid & 31;
    int gid  = lane >> 2, tig = lane & 3;
    int mwarp = (wid & 1) * 64;       // 2 warp-rows
    int nwarp = (wid >> 1) * 32;      // 4 warp-cols

    // decode upper-triangular tile (i <= j) from linear block id
    int ti = 0, rem = blockIdx.x;
    while (rem >= NTILE - ti){ rem -= NTILE - ti; ti++; }
    int tj = ti + rem;
    int rb = ti * 128, cb = tj * 128;

    float acc[4][4][4];
    #pragma unroll
    for (int a = 0; a < 4; a++)
        #pragma unroll
        for (int b = 0; b < 4; b++)
            #pragma unroll
            for (int c = 0; c < 4; c++) acc[a][b][c] = 0.f;

    tile_load(ZH, s0, s0 + TILEB, rb, cb, 0, tid);
    cp_commit();

    for (int it = 0; it < NIT; it++){
        int s = it & 1;
        if (it + 1 < NIT){
            int ns = (it + 1) & 1;
            tile_load(ZH, s0 + ns*BUFB, s0 + ns*BUFB + TILEB, rb, cb, it + 1, tid);
            cp_commit();
            cp_wait<1>();
        } else {
            cp_wait<0>();
        }
        __syncthreads();

        const uint32_t* As32 = (const uint32_t*)(dsm + s*BUFB);
        const uint32_t* Bs32 = (const uint32_t*)(dsm + s*BUFB + TILEB);

        #pragma unroll
        for (int kk = 0; kk < BK/16; kk++){
            uint32_t af[4][4];
            #pragma unroll
            for (int mi = 0; mi < 4; mi++){
                const uint32_t* base = As32 + (size_t)(mwarp + mi*16 + gid)*(SROW/2) + tig + kk*8;
                af[mi][0] = base[0];
                af[mi][1] = base[8*(SROW/2)];
                af[mi][2] = base[4];
                af[mi][3] = base[8*(SROW/2) + 4];
            }
            uint32_t bf[4][2];
            #pragma unroll
            for (int ni = 0; ni < 4; ni++){
                const uint32_t* bb = Bs32 + (size_t)(nwarp + ni*8 + gid)*(SROW/2) + tig + kk*8;
                bf[ni][0] = bb[0];
                bf[ni][1] = bb[4];
            }
            #pragma unroll
            for (int mi = 0; mi < 4; mi++)
                #pragma unroll
                for (int ni = 0; ni < 4; ni++)
                    mma16816(acc[mi][ni], af[mi], bf[ni]);
        }
        __syncthreads();
    }

    // direct write (rows rb.., cols cb..)
    #pragma unroll
    for (int mi = 0; mi < 4; mi++){
        int r0 = rb + mwarp + mi*16 + gid;
        int r1 = r0 + 8;
        #pragma unroll
        for (int ni = 0; ni < 4; ni++){
            int col = cb + nwarp + ni*8 + tig*2;
            if (col + 1 < Nn){
                if (r0 < Nn)
                    *(float2*)(C + (size_t)r0*Nn + col) = make_float2(acc[mi][ni][0], acc[mi][ni][1]);
                if (r1 < Nn)
                    *(float2*)(C + (size_t)r1*Nn + col) = make_float2(acc[mi][ni][2], acc[mi][ni][3]);
            }
        }
    }

    // mirror write for off-diagonal tiles: C[cb+c, rb+r] = tile[r][c]
    if (ti != tj){
        float* st = (float*)dsm;          // 128 x 128, stride 129 (conflict-free transpose read)
        __syncthreads();                  // mainloop smem no longer needed
        #pragma unroll
        for (int mi = 0; mi < 4; mi++){
            int r0 = mwarp + mi*16 + gid;
            int r1 = r0 + 8;
            #pragma unroll
            for (int ni = 0; ni < 4; ni++){
                int cl = nwarp + ni*8 + tig*2;
                st[r0*129 + cl]     = acc[mi][ni][0];
                st[r0*129 + cl + 1] = acc[mi][ni][1];
                st[r1*129 + cl]     = acc[mi][ni][2];
                st[r1*129 + cl + 1] = acc[mi][ni][3];
            }
        }
        __syncthreads();
        for (int idx = tid; idx < 128*128; idx += 256){
            int orow = idx >> 7;          // = original col
            int ocol = idx & 127;         // = original row
            int grow = cb + orow, gcol = rb + ocol;
            if (grow < Nn && gcol < Nn)
                C[(size_t)grow*Nn + gcol] = st[ocol*129 + orow];
        }
    }
}

// ---------------- launch ----------------
extern "C" void kernel_launch(void* const* d_in, const int* in_sizes, int n_in,
                              void* d_out, int out_size){
    const float*     x   = (const float*)d_in[0];
    const void*      ei  = d_in[1];
    const float*     ea  = (const float*)d_in[2];
    const float*     W1  = (const float*)d_in[3];
    const float*     as1 = (const float*)d_in[4];
    const float*     ad1 = (const float*)d_in[5];
    const float*     We1 = (const float*)d_in[6];
    const float*     ae1 = (const float*)d_in[7];
    const float*     b1  = (const float*)d_in[8];
    const float*     W2  = (const float*)d_in[9];
    const float*     as2 = (const float*)d_in[10];
    const float*     ad2 = (const float*)d_in[11];
    const float*     We2 = (const float*)d_in[12];
    const float*     ae2 = (const float*)d_in[13];
    const float*     b2  = (const float*)d_in[14];
    const float*     Wp  = (const float*)d_in[15];
    const float*     bp  = (const float*)d_in[16];

    int E  = in_sizes[1]/2;
    if (E > EBASE) E = EBASE;
    int ET = E + Nn;

    float* out  = (float*)d_out;
    float* Ahat = out;
    float* P    = out + (size_t)Nn*Nn;
    float* Zo   = P + (size_t)Nn*NKC;

    float *h1, *hl1, *h2p, *zb;
    float *pas1, *pad1, *pas2, *pad2;
    unsigned short *zH;
    int *degp;
    cudaGetSymbolAddress((void**)&h1,   g_h1);
    cudaGetSymbolAddress((void**)&hl1,  g_hl1);
    cudaGetSymbolAddress((void**)&h2p,  g_h2);
    cudaGetSymbolAddress((void**)&zb,   g_z);
    cudaGetSymbolAddress((void**)&pas1, g_as1);
    cudaGetSymbolAddress((void**)&pad1, g_ad1);
    cudaGetSymbolAddress((void**)&pas2, g_as2);
    cudaGetSymbolAddress((void**)&pad2, g_ad2);
    cudaGetSymbolAddress((void**)&zH,   g_zH);
    cudaGetSymbolAddress((void**)&degp, g_deg);

    k_detect<<<1, 32>>>((const unsigned*)ei);
    k_convert<<<(2*E + 255)/256, 256>>>(ei, 2*E);
    k_ae<<<1, 32>>>(We1, ae1, We2, ae2);

    // -------- CSR build (once; shared by both layers) --------
    k_zero<<<(Nn + 255)/256, 256>>>((float*)degp, Nn);
    k_hist<<<(ET + 255)/256, 256>>>(E);
    k_scan<<<1, SCT>>>();
    k_fill<<<(ET + 255)/256, 256>>>(E);

    // -------- layer 1 --------
    gemm64<true><<<dim3(HC1/64, (Nn+63)/64), 256>>>(x, W1, h1, Nn, HC1, INC);
    k_attn<<<(Nn*NH*32 + 255)/256, 256>>>(h1, as1, ad1, pas1, pad1, HIDC);
    k_gather2<HIDC,1><<<Nn, NH*HIDC>>>(h1, ea, pas1, pad1, b1, hl1, E, 0);

    // -------- layer 2 --------
    gemm64<false><<<dim3(HC2/64, (Nn+63)/64), 256>>>(hl1, W2, h2p, Nn, HC2, HC1);
    k_attn<<<(Nn*NH*32 + 255)/256, 256>>>(h2p, as2, ad2, pas2, pad2, OUTC);
    k_gather2<OUTC,0><<<Nn, NH*OUTC>>>(h2p, ea, pas2, pad2, b2, hl1, E, NH);  // output -> hl1

    // -------- head --------
    k_norm<<<(Nn*32 + 255)/256, 256>>>(hl1, zb, Zo);
    k_p<<<(Nn + 255)/256, 256>>>(zb, Wp, bp, P);
    k_pack<<<(MPAD*HC2 + 255)/256, 256>>>(zb, zH);

    const int SYRK_SMEM = 2*BUFB;   // 73728 B (mainloop) >= 128*129*4 (transpose stage)
    cudaFuncSetAttribute(k_syrk_mma, cudaFuncAttributeMaxDynamicSharedMemorySize, SYRK_SMEM);
    k_syrk_mma<<<NTRI, 256, SYRK_SMEM>>>((const char*)zH, Ahat);
}